// round 1
// baseline (speedup 1.0000x reference)
#include <cuda_runtime.h>
#include <math.h>

#define B_ 2
#define S_ 2048
#define D_ 2048
#define H_ 16
#define KVH_ 4
#define HD_ 128
#define REP_ (H_/KVH_)

// Scratch (device globals: allocation-free)
__device__ float g_qproj[B_*S_*H_*HD_];    // [B*S, H*HD]
__device__ float g_kproj[B_*S_*KVH_*HD_];  // [B*S, KVH*HD]
__device__ float g_vproj[B_*S_*KVH_*HD_];  // [B*S, KVH*HD]
__device__ float g_attn [B_*S_*H_*HD_];    // [B*S, H*HD]

// ---------------------------------------------------------------------------
// SGEMM: C[M,N] = A[M,K] @ W[K,N], all row-major, fp32.
// BM=128, BN=128, BK=16, 256 threads, 8x8 microtile.
// Requires M%128==0, N%128==0, K%16==0 (true for all our shapes).
// ---------------------------------------------------------------------------
#define BM 128
#define BN 128
#define BK 16
#define TM 8
#define TN 8

__global__ __launch_bounds__(256) void sgemm_kernel(
    const float* __restrict__ A, const float* __restrict__ W,
    float* __restrict__ C, int M, int N, int K)
{
    __shared__ float As[BK][BM];
    __shared__ float Bs[BK][BN];

    const int tid = threadIdx.x;
    const int tx = tid & 15;        // 0..15 (col group)
    const int ty = tid >> 4;        // 0..15 (row group)
    const int bm = blockIdx.y * BM;
    const int bn = blockIdx.x * BN;

    float acc[TM][TN];
    #pragma unroll
    for (int i = 0; i < TM; i++)
        #pragma unroll
        for (int j = 0; j < TN; j++) acc[i][j] = 0.f;

    for (int k0 = 0; k0 < K; k0 += BK) {
        // Load A tile (BM x BK) and B tile (BK x BN), 2 float4 each per thread
        #pragma unroll
        for (int l = 0; l < 2; l++) {
            int idx = tid + l * 256;            // 0..511 float4 id
            int r  = idx >> 2;                  // 0..127
            int c4 = (idx & 3) << 2;            // 0,4,8,12
            float4 av = *reinterpret_cast<const float4*>(
                &A[(long)(bm + r) * K + k0 + c4]);
            As[c4+0][r] = av.x; As[c4+1][r] = av.y;
            As[c4+2][r] = av.z; As[c4+3][r] = av.w;

            int rb  = idx >> 5;                 // 0..15
            int cb4 = (idx & 31) << 2;          // 0..124
            float4 bv = *reinterpret_cast<const float4*>(
                &W[(long)(k0 + rb) * N + bn + cb4]);
            *reinterpret_cast<float4*>(&Bs[rb][cb4]) = bv;
        }
        __syncthreads();

        #pragma unroll
        for (int k = 0; k < BK; k++) {
            float ar[TM], br[TN];
            #pragma unroll
            for (int i = 0; i < TM; i++) ar[i] = As[k][ty*TM + i];
            #pragma unroll
            for (int j = 0; j < TN; j++) br[j] = Bs[k][tx*TN + j];
            #pragma unroll
            for (int i = 0; i < TM; i++)
                #pragma unroll
                for (int j = 0; j < TN; j++)
                    acc[i][j] = fmaf(ar[i], br[j], acc[i][j]);
        }
        __syncthreads();
    }

    #pragma unroll
    for (int i = 0; i < TM; i++) {
        long row = bm + ty*TM + i;
        #pragma unroll
        for (int j4 = 0; j4 < TN; j4 += 4) {
            float4 v = make_float4(acc[i][j4], acc[i][j4+1], acc[i][j4+2], acc[i][j4+3]);
            *reinterpret_cast<float4*>(&C[row * N + bn + tx*TN + j4]) = v;
        }
    }
}

// ---------------------------------------------------------------------------
// RoPE (in-place). One thread per (row, head, i<64) pair.
// row = b*S + s ; layout [B*S, nheads*HD]
// ---------------------------------------------------------------------------
__global__ void rope_kernel(float* __restrict__ q, int nheads)
{
    long idx = (long)blockIdx.x * blockDim.x + threadIdx.x;
    int i = (int)(idx & 63);
    long t = idx >> 6;
    int h = (int)(t % nheads);
    long row = t / nheads;
    int s = (int)(row % S_);

    float inv = powf(10000.0f, -((float)(2*i)) / (float)HD_);
    float ang = (float)s * inv;
    float sn, cs;
    sincosf(ang, &sn, &cs);

    float* p = q + row * ((long)nheads * HD_) + (long)h * HD_;
    float x1 = p[i];
    float x2 = p[i + 64];
    p[i]      = x1 * cs - x2 * sn;
    p[i + 64] = x2 * cs + x1 * sn;
}

// ---------------------------------------------------------------------------
// Flash attention, fp32, causal. Grid (S/64, H, B), 256 threads (8 warps).
// Each warp owns 8 query rows. BLOCK_N = 64 kv cols per tile.
// Smem: Qs,Ks,Vs each 64 x 129 floats (padded, conflict-free).
// ---------------------------------------------------------------------------
#define ATTN_STRIDE 129
#define ATTN_SMEM (3 * 64 * ATTN_STRIDE * 4)

__global__ __launch_bounds__(256) void attn_kernel()
{
    extern __shared__ float smem[];
    float* Qs = smem;
    float* Ks = smem + 64 * ATTN_STRIDE;
    float* Vs = smem + 2 * 64 * ATTN_STRIDE;

    const int qt = blockIdx.x;   // query tile
    const int h  = blockIdx.y;
    const int b  = blockIdx.z;
    const int kvh = h / REP_;

    const int tid = threadIdx.x;
    const int lane = tid & 31;
    const int w = tid >> 5;

    const float scale = 0.08838834764831845f;  // 1/sqrt(128)

    // Load Q tile (pre-scaled)
    for (int e = tid; e < 64 * HD_; e += 256) {
        int r = e >> 7, d = e & 127;
        long grow = (long)(b * S_ + qt * 64 + r);
        Qs[r * ATTN_STRIDE + d] =
            g_qproj[grow * (H_ * HD_) + h * HD_ + d] * scale;
    }

    float m_i[8], l_i[8], acc[8][4];
    #pragma unroll
    for (int rr = 0; rr < 8; rr++) {
        m_i[rr] = -1e30f; l_i[rr] = 0.f;
        #pragma unroll
        for (int j = 0; j < 4; j++) acc[rr][j] = 0.f;
    }

    for (int kt = 0; kt <= qt; kt++) {
        __syncthreads();   // protect smem from previous iteration's readers
        for (int e = tid; e < 64 * HD_; e += 256) {
            int r = e >> 7, d = e & 127;
            long grow = (long)(b * S_ + kt * 64 + r);
            Ks[r * ATTN_STRIDE + d] = g_kproj[grow * (KVH_ * HD_) + kvh * HD_ + d];
            Vs[r * ATTN_STRIDE + d] = g_vproj[grow * (KVH_ * HD_) + kvh * HD_ + d];
        }
        __syncthreads();

        // ---- scores: 8 rows x 2 cols per lane ----
        float s0[8], s1[8];
        #pragma unroll
        for (int rr = 0; rr < 8; rr++) { s0[rr] = 0.f; s1[rr] = 0.f; }

        const float* krow0 = &Ks[lane * ATTN_STRIDE];
        const float* krow1 = &Ks[(lane + 32) * ATTN_STRIDE];
        const float* qbase = &Qs[(w * 8) * ATTN_STRIDE];
        #pragma unroll 4
        for (int i = 0; i < HD_; i++) {
            float k0 = krow0[i], k1 = krow1[i];
            #pragma unroll
            for (int rr = 0; rr < 8; rr++) {
                float qv = qbase[rr * ATTN_STRIDE + i];
                s0[rr] = fmaf(qv, k0, s0[rr]);
                s1[rr] = fmaf(qv, k1, s1[rr]);
            }
        }

        // ---- causal mask (only diagonal tile) ----
        const int qrow0 = qt * 64 + w * 8;
        if (kt == qt) {
            int c0 = kt * 64 + lane;
            int c1 = c0 + 32;
            #pragma unroll
            for (int rr = 0; rr < 8; rr++) {
                int qr = qrow0 + rr;
                if (c0 > qr) s0[rr] = -1e30f;
                if (c1 > qr) s1[rr] = -1e30f;
            }
        }

        // ---- online softmax update ----
        float p0[8], p1[8], alpha[8];
        #pragma unroll
        for (int rr = 0; rr < 8; rr++) {
            float mt = fmaxf(s0[rr], s1[rr]);
            #pragma unroll
            for (int o = 16; o > 0; o >>= 1)
                mt = fmaxf(mt, __shfl_xor_sync(0xffffffffu, mt, o));
            float mnew = fmaxf(m_i[rr], mt);
            p0[rr] = expf(s0[rr] - mnew);
            p1[rr] = expf(s1[rr] - mnew);
            float rs = p0[rr] + p1[rr];
            #pragma unroll
            for (int o = 16; o > 0; o >>= 1)
                rs += __shfl_xor_sync(0xffffffffu, rs, o);
            alpha[rr] = expf(m_i[rr] - mnew);
            l_i[rr] = l_i[rr] * alpha[rr] + rs;
            m_i[rr] = mnew;
        }
        #pragma unroll
        for (int rr = 0; rr < 8; rr++)
            #pragma unroll
            for (int j = 0; j < 4; j++)
                acc[rr][j] *= alpha[rr];

        // ---- PV: V smem reads reused across all 8 rows ----
        for (int c = 0; c < 32; c++) {
            float pa[8], pb[8];
            #pragma unroll
            for (int rr = 0; rr < 8; rr++) {
                pa[rr] = __shfl_sync(0xffffffffu, p0[rr], c);
                pb[rr] = __shfl_sync(0xffffffffu, p1[rr], c);
            }
            #pragma unroll
            for (int j = 0; j < 4; j++) {
                float v0 = Vs[c * ATTN_STRIDE + j * 32 + lane];
                float v1 = Vs[(c + 32) * ATTN_STRIDE + j * 32 + lane];
                #pragma unroll
                for (int rr = 0; rr < 8; rr++)
                    acc[rr][j] = fmaf(pa[rr], v0, fmaf(pb[rr], v1, acc[rr][j]));
            }
        }
    }

    // ---- epilogue ----
    #pragma unroll
    for (int rr = 0; rr < 8; rr++) {
        float invl = 1.0f / l_i[rr];
        int qr = qt * 64 + w * 8 + rr;
        long base = (long)(b * S_ + qr) * (H_ * HD_) + h * HD_;
        #pragma unroll
        for (int j = 0; j < 4; j++)
            g_attn[base + j * 32 + lane] = acc[rr][j] * invl;
    }
}

// ---------------------------------------------------------------------------
extern "C" void kernel_launch(void* const* d_in, const int* in_sizes, int n_in,
                              void* d_out, int out_size)
{
    const float* x  = (const float*)d_in[0];
    const float* Wq = (const float*)d_in[1];
    const float* Wk = (const float*)d_in[2];
    const float* Wv = (const float*)d_in[3];
    const float* Wo = (const float*)d_in[4];
    float* out = (float*)d_out;

    float *qproj, *kproj, *vproj, *attn;
    cudaGetSymbolAddress((void**)&qproj, g_qproj);
    cudaGetSymbolAddress((void**)&kproj, g_kproj);
    cudaGetSymbolAddress((void**)&vproj, g_vproj);
    cudaGetSymbolAddress((void**)&attn,  g_attn);

    const int M = B_ * S_;   // 4096

    // QKV projections
    sgemm_kernel<<<dim3((H_*HD_)/BN,   M/BM), 256>>>(x, Wq, qproj, M, H_*HD_,   D_);
    sgemm_kernel<<<dim3((KVH_*HD_)/BN, M/BM), 256>>>(x, Wk, kproj, M, KVH_*HD_, D_);
    sgemm_kernel<<<dim3((KVH_*HD_)/BN, M/BM), 256>>>(x, Wv, vproj, M, KVH_*HD_, D_);

    // RoPE in-place on Q and K
    rope_kernel<<<(B_*S_*H_*64)/256,   256>>>(qproj, H_);
    rope_kernel<<<(B_*S_*KVH_*64)/256, 256>>>(kproj, KVH_);

    // Flash attention
    cudaFuncSetAttribute(attn_kernel,
                         cudaFuncAttributeMaxDynamicSharedMemorySize, ATTN_SMEM);
    attn_kernel<<<dim3(S_/64, H_, B_), 256, ATTN_SMEM>>>();

    // Output projection
    sgemm_kernel<<<dim3(D_/BN, M/BM), 256>>>(attn, Wo, out, M, D_, D_);
}

// round 2
// speedup vs baseline: 1.6703x; 1.6703x over previous
#include <cuda_runtime.h>
#include <math.h>

#define B_ 2
#define S_ 2048
#define D_ 2048
#define H_ 16
#define KVH_ 4
#define HD_ 128
#define REP_ (H_/KVH_)

// Scratch (device globals: allocation-free)
__device__ float g_qproj[B_*S_*H_*HD_];    // [B*S, H*HD]
__device__ float g_kproj[B_*S_*KVH_*HD_];  // [B*S, KVH*HD]
__device__ float g_vproj[B_*S_*KVH_*HD_];  // [B*S, KVH*HD]
__device__ float g_attn [B_*S_*H_*HD_];    // [B*S, H*HD]

// ---------------------------------------------------------------------------
// TF32 tensor-core GEMM: C[M,N] = A[M,K] @ W[K,N], row-major fp32 in/out.
// BM=128, BN=128, BK=32, 256 threads (8 warps, 2x4), warp tile 64x32,
// mma.sync.m16n8k8.tf32. Inputs rounded to tf32 (cvt.rna) at smem fill.
// Requires M%128==0, N%128==0, K%32==0.
// ---------------------------------------------------------------------------
#define BM 128
#define BN 128
#define BK 32
#define AS_STRIDE 36    // As[BM][36]  -> conflict-free frag loads + stores
#define BS_STRIDE 136   // Bs[BK][136] -> conflict-free frag loads + stores

__device__ __forceinline__ float to_tf32(float x) {
    float r;
    asm("cvt.rna.tf32.f32 %0, %1;" : "=f"(r) : "f"(x));
    return r;
}

__device__ __forceinline__ void mma_tf32(
    float* c, const unsigned* a, const unsigned* b)
{
    asm volatile(
        "mma.sync.aligned.m16n8k8.row.col.f32.tf32.tf32.f32 "
        "{%0,%1,%2,%3}, {%4,%5,%6,%7}, {%8,%9}, {%0,%1,%2,%3};"
        : "+f"(c[0]), "+f"(c[1]), "+f"(c[2]), "+f"(c[3])
        : "r"(a[0]), "r"(a[1]), "r"(a[2]), "r"(a[3]),
          "r"(b[0]), "r"(b[1]));
}

__global__ __launch_bounds__(256) void tf32_gemm_kernel(
    const float* __restrict__ A, const float* __restrict__ W,
    float* __restrict__ C, int M, int N, int K)
{
    __shared__ float As[BM * AS_STRIDE];   // 18432 B
    __shared__ float Bs[BK * BS_STRIDE];   // 17408 B

    const int tid  = threadIdx.x;
    const int lane = tid & 31;
    const int warp = tid >> 5;
    const int wm   = warp >> 2;            // 0..1  -> m offset 64*wm
    const int wn   = warp & 3;             // 0..3  -> n offset 32*wn
    const int bm   = blockIdx.y * BM;
    const int bn   = blockIdx.x * BN;

    float acc[4][4][4];
    #pragma unroll
    for (int mt = 0; mt < 4; mt++)
        #pragma unroll
        for (int nt = 0; nt < 4; nt++)
            #pragma unroll
            for (int i = 0; i < 4; i++) acc[mt][nt][i] = 0.f;

    const int lq = lane >> 2;   // 0..7
    const int lr = lane & 3;    // 0..3

    for (int k0 = 0; k0 < K; k0 += BK) {
        // ---- A tile: 128 x 32 (8 float4 per row), 4 float4 per thread ----
        #pragma unroll
        for (int l = 0; l < 4; l++) {
            int idx = tid + l * 256;        // 0..1023
            int r   = idx >> 3;
            int c4  = (idx & 7) << 2;
            float4 v = *reinterpret_cast<const float4*>(
                &A[(long)(bm + r) * K + k0 + c4]);
            v.x = to_tf32(v.x); v.y = to_tf32(v.y);
            v.z = to_tf32(v.z); v.w = to_tf32(v.w);
            *reinterpret_cast<float4*>(&As[r * AS_STRIDE + c4]) = v;
        }
        // ---- B tile: 32 x 128 (32 float4 per row), 4 float4 per thread ----
        #pragma unroll
        for (int l = 0; l < 4; l++) {
            int idx = tid + l * 256;
            int kr  = idx >> 5;
            int c4  = (idx & 31) << 2;
            float4 v = *reinterpret_cast<const float4*>(
                &W[(long)(k0 + kr) * N + bn + c4]);
            v.x = to_tf32(v.x); v.y = to_tf32(v.y);
            v.z = to_tf32(v.z); v.w = to_tf32(v.w);
            *reinterpret_cast<float4*>(&Bs[kr * BS_STRIDE + c4]) = v;
        }
        __syncthreads();

        #pragma unroll
        for (int ks = 0; ks < BK; ks += 8) {
            unsigned a[4][4], b[4][2];
            #pragma unroll
            for (int mt = 0; mt < 4; mt++) {
                int row = wm * 64 + mt * 16 + lq;
                a[mt][0] = __float_as_uint(As[row * AS_STRIDE + ks + lr]);
                a[mt][1] = __float_as_uint(As[(row + 8) * AS_STRIDE + ks + lr]);
                a[mt][2] = __float_as_uint(As[row * AS_STRIDE + ks + lr + 4]);
                a[mt][3] = __float_as_uint(As[(row + 8) * AS_STRIDE + ks + lr + 4]);
            }
            #pragma unroll
            for (int nt = 0; nt < 4; nt++) {
                int col = wn * 32 + nt * 8 + lq;
                b[nt][0] = __float_as_uint(Bs[(ks + lr) * BS_STRIDE + col]);
                b[nt][1] = __float_as_uint(Bs[(ks + lr + 4) * BS_STRIDE + col]);
            }
            #pragma unroll
            for (int mt = 0; mt < 4; mt++)
                #pragma unroll
                for (int nt = 0; nt < 4; nt++)
                    mma_tf32(acc[mt][nt], a[mt], b[nt]);
        }
        __syncthreads();
    }

    // ---- epilogue ----
    #pragma unroll
    for (int mt = 0; mt < 4; mt++) {
        int row = bm + wm * 64 + mt * 16 + lq;
        #pragma unroll
        for (int nt = 0; nt < 4; nt++) {
            int col = bn + wn * 32 + nt * 8 + 2 * lr;
            float2 v0 = make_float2(acc[mt][nt][0], acc[mt][nt][1]);
            float2 v1 = make_float2(acc[mt][nt][2], acc[mt][nt][3]);
            *reinterpret_cast<float2*>(&C[(long)row * N + col]) = v0;
            *reinterpret_cast<float2*>(&C[(long)(row + 8) * N + col]) = v1;
        }
    }
}

// ---------------------------------------------------------------------------
// RoPE (in-place). One thread per (row, head, i<64) pair.
// ---------------------------------------------------------------------------
__global__ void rope_kernel(float* __restrict__ q, int nheads)
{
    long idx = (long)blockIdx.x * blockDim.x + threadIdx.x;
    int i = (int)(idx & 63);
    long t = idx >> 6;
    int h = (int)(t % nheads);
    long row = t / nheads;
    int s = (int)(row % S_);

    float inv = powf(10000.0f, -((float)(2*i)) / (float)HD_);
    float ang = (float)s * inv;
    float sn, cs;
    sincosf(ang, &sn, &cs);

    float* p = q + row * ((long)nheads * HD_) + (long)h * HD_;
    float x1 = p[i];
    float x2 = p[i + 64];
    p[i]      = x1 * cs - x2 * sn;
    p[i + 64] = x2 * cs + x1 * sn;
}

// ---------------------------------------------------------------------------
// Flash attention, fp32, causal. Grid (S/64, H, B), 256 threads (8 warps).
// ---------------------------------------------------------------------------
#define ATTN_STRIDE 129
#define ATTN_SMEM (3 * 64 * ATTN_STRIDE * 4)

__global__ __launch_bounds__(256) void attn_kernel()
{
    extern __shared__ float smem[];
    float* Qs = smem;
    float* Ks = smem + 64 * ATTN_STRIDE;
    float* Vs = smem + 2 * 64 * ATTN_STRIDE;

    const int qt = blockIdx.x;
    const int h  = blockIdx.y;
    const int b  = blockIdx.z;
    const int kvh = h / REP_;

    const int tid = threadIdx.x;
    const int lane = tid & 31;
    const int w = tid >> 5;

    const float scale = 0.08838834764831845f;  // 1/sqrt(128)

    for (int e = tid; e < 64 * HD_; e += 256) {
        int r = e >> 7, d = e & 127;
        long grow = (long)(b * S_ + qt * 64 + r);
        Qs[r * ATTN_STRIDE + d] =
            g_qproj[grow * (H_ * HD_) + h * HD_ + d] * scale;
    }

    float m_i[8], l_i[8], acc[8][4];
    #pragma unroll
    for (int rr = 0; rr < 8; rr++) {
        m_i[rr] = -1e30f; l_i[rr] = 0.f;
        #pragma unroll
        for (int j = 0; j < 4; j++) acc[rr][j] = 0.f;
    }

    for (int kt = 0; kt <= qt; kt++) {
        __syncthreads();
        for (int e = tid; e < 64 * HD_; e += 256) {
            int r = e >> 7, d = e & 127;
            long grow = (long)(b * S_ + kt * 64 + r);
            Ks[r * ATTN_STRIDE + d] = g_kproj[grow * (KVH_ * HD_) + kvh * HD_ + d];
            Vs[r * ATTN_STRIDE + d] = g_vproj[grow * (KVH_ * HD_) + kvh * HD_ + d];
        }
        __syncthreads();

        float s0[8], s1[8];
        #pragma unroll
        for (int rr = 0; rr < 8; rr++) { s0[rr] = 0.f; s1[rr] = 0.f; }

        const float* krow0 = &Ks[lane * ATTN_STRIDE];
        const float* krow1 = &Ks[(lane + 32) * ATTN_STRIDE];
        const float* qbase = &Qs[(w * 8) * ATTN_STRIDE];
        #pragma unroll 4
        for (int i = 0; i < HD_; i++) {
            float k0 = krow0[i], k1 = krow1[i];
            #pragma unroll
            for (int rr = 0; rr < 8; rr++) {
                float qv = qbase[rr * ATTN_STRIDE + i];
                s0[rr] = fmaf(qv, k0, s0[rr]);
                s1[rr] = fmaf(qv, k1, s1[rr]);
            }
        }

        const int qrow0 = qt * 64 + w * 8;
        if (kt == qt) {
            int c0 = kt * 64 + lane;
            int c1 = c0 + 32;
            #pragma unroll
            for (int rr = 0; rr < 8; rr++) {
                int qr = qrow0 + rr;
                if (c0 > qr) s0[rr] = -1e30f;
                if (c1 > qr) s1[rr] = -1e30f;
            }
        }

        float p0[8], p1[8], alpha[8];
        #pragma unroll
        for (int rr = 0; rr < 8; rr++) {
            float mt = fmaxf(s0[rr], s1[rr]);
            #pragma unroll
            for (int o = 16; o > 0; o >>= 1)
                mt = fmaxf(mt, __shfl_xor_sync(0xffffffffu, mt, o));
            float mnew = fmaxf(m_i[rr], mt);
            p0[rr] = expf(s0[rr] - mnew);
            p1[rr] = expf(s1[rr] - mnew);
            float rs = p0[rr] + p1[rr];
            #pragma unroll
            for (int o = 16; o > 0; o >>= 1)
                rs += __shfl_xor_sync(0xffffffffu, rs, o);
            alpha[rr] = expf(m_i[rr] - mnew);
            l_i[rr] = l_i[rr] * alpha[rr] + rs;
            m_i[rr] = mnew;
        }
        #pragma unroll
        for (int rr = 0; rr < 8; rr++)
            #pragma unroll
            for (int j = 0; j < 4; j++)
                acc[rr][j] *= alpha[rr];

        for (int c = 0; c < 32; c++) {
            float pa[8], pb[8];
            #pragma unroll
            for (int rr = 0; rr < 8; rr++) {
                pa[rr] = __shfl_sync(0xffffffffu, p0[rr], c);
                pb[rr] = __shfl_sync(0xffffffffu, p1[rr], c);
            }
            #pragma unroll
            for (int j = 0; j < 4; j++) {
                float v0 = Vs[c * ATTN_STRIDE + j * 32 + lane];
                float v1 = Vs[(c + 32) * ATTN_STRIDE + j * 32 + lane];
                #pragma unroll
                for (int rr = 0; rr < 8; rr++)
                    acc[rr][j] = fmaf(pa[rr], v0, fmaf(pb[rr], v1, acc[rr][j]));
            }
        }
    }

    #pragma unroll
    for (int rr = 0; rr < 8; rr++) {
        float invl = 1.0f / l_i[rr];
        int qr = qt * 64 + w * 8 + rr;
        long base = (long)(b * S_ + qr) * (H_ * HD_) + h * HD_;
        #pragma unroll
        for (int j = 0; j < 4; j++)
            g_attn[base + j * 32 + lane] = acc[rr][j] * invl;
    }
}

// ---------------------------------------------------------------------------
extern "C" void kernel_launch(void* const* d_in, const int* in_sizes, int n_in,
                              void* d_out, int out_size)
{
    const float* x  = (const float*)d_in[0];
    const float* Wq = (const float*)d_in[1];
    const float* Wk = (const float*)d_in[2];
    const float* Wv = (const float*)d_in[3];
    const float* Wo = (const float*)d_in[4];
    float* out = (float*)d_out;

    float *qproj, *kproj, *vproj, *attn;
    cudaGetSymbolAddress((void**)&qproj, g_qproj);
    cudaGetSymbolAddress((void**)&kproj, g_kproj);
    cudaGetSymbolAddress((void**)&vproj, g_vproj);
    cudaGetSymbolAddress((void**)&attn,  g_attn);

    const int M = B_ * S_;   // 4096

    // QKV projections (tf32 tensor cores)
    tf32_gemm_kernel<<<dim3((H_*HD_)/BN,   M/BM), 256>>>(x, Wq, qproj, M, H_*HD_,   D_);
    tf32_gemm_kernel<<<dim3((KVH_*HD_)/BN, M/BM), 256>>>(x, Wk, kproj, M, KVH_*HD_, D_);
    tf32_gemm_kernel<<<dim3((KVH_*HD_)/BN, M/BM), 256>>>(x, Wv, vproj, M, KVH_*HD_, D_);

    // RoPE in-place on Q and K
    rope_kernel<<<(B_*S_*H_*64)/256,   256>>>(qproj, H_);
    rope_kernel<<<(B_*S_*KVH_*64)/256, 256>>>(kproj, KVH_);

    // Flash attention (fp32)
    cudaFuncSetAttribute(attn_kernel,
                         cudaFuncAttributeMaxDynamicSharedMemorySize, ATTN_SMEM);
    attn_kernel<<<dim3(S_/64, H_, B_), 256, ATTN_SMEM>>>();

    // Output projection (tf32 tensor cores)
    tf32_gemm_kernel<<<dim3(D_/BN, M/BM), 256>>>(attn, Wo, out, M, D_, D_);
}

// round 4
// speedup vs baseline: 2.9737x; 1.7803x over previous
#include <cuda_runtime.h>
#include <math.h>

#define B_ 2
#define S_ 2048
#define D_ 2048
#define H_ 16
#define KVH_ 4
#define HD_ 128
#define REP_ (H_/KVH_)

// Scratch (device globals: allocation-free)
__device__ float g_qproj[B_*S_*H_*HD_];    // [B*S, H*HD]
__device__ float g_kproj[B_*S_*KVH_*HD_];  // [B*S, KVH*HD]
__device__ float g_vproj[B_*S_*KVH_*HD_];  // [B*S, KVH*HD]
__device__ float g_attn [B_*S_*H_*HD_];    // [B*S, H*HD]

__device__ __forceinline__ float to_tf32(float x) {
    float r;
    asm("cvt.rna.tf32.f32 %0, %1;" : "=f"(r) : "f"(x));
    return r;
}
__device__ __forceinline__ float ex2f(float x) {
    float r;
    asm("ex2.approx.ftz.f32 %0, %1;" : "=f"(r) : "f"(x));
    return r;
}
__device__ __forceinline__ void mma_tf32(
    float* c, const unsigned* a, const unsigned* b)
{
    asm volatile(
        "mma.sync.aligned.m16n8k8.row.col.f32.tf32.tf32.f32 "
        "{%0,%1,%2,%3}, {%4,%5,%6,%7}, {%8,%9}, {%0,%1,%2,%3};"
        : "+f"(c[0]), "+f"(c[1]), "+f"(c[2]), "+f"(c[3])
        : "r"(a[0]), "r"(a[1]), "r"(a[2]), "r"(a[3]),
          "r"(b[0]), "r"(b[1]));
}

// ---------------------------------------------------------------------------
// TF32 double-buffered GEMM: C[M,N] = A[M,K] @ W[K,N], row-major fp32.
// BM=128, BN=128, BK=32, 256 threads (8 warps 2x4), warp tile 64x32.
// ---------------------------------------------------------------------------
#define BM 128
#define BN 128
#define BK 32
#define AS_STRIDE 36
#define BS_STRIDE 136

__global__ __launch_bounds__(256) void tf32_gemm_kernel(
    const float* __restrict__ A, const float* __restrict__ W,
    float* __restrict__ C, int M, int N, int K)
{
    __shared__ float As[2][BM * AS_STRIDE];
    __shared__ float Bs[2][BK * BS_STRIDE];

    const int tid  = threadIdx.x;
    const int lane = tid & 31;
    const int warp = tid >> 5;
    const int wm   = warp >> 2;
    const int wn   = warp & 3;
    const int bm   = blockIdx.y * BM;
    const int bn   = blockIdx.x * BN;
    const int lq = lane >> 2;
    const int lr = lane & 3;

    float acc[4][4][4];
    #pragma unroll
    for (int mt = 0; mt < 4; mt++)
        #pragma unroll
        for (int nt = 0; nt < 4; nt++)
            #pragma unroll
            for (int i = 0; i < 4; i++) acc[mt][nt][i] = 0.f;

    float4 pa[4], pb[4];

    // prologue: load tile 0
    #pragma unroll
    for (int l = 0; l < 4; l++) {
        int idx = tid + l * 256;
        int r = idx >> 3, c4 = (idx & 7) << 2;
        pa[l] = *reinterpret_cast<const float4*>(&A[(long)(bm + r) * K + c4]);
        int kr = idx >> 5, cb = (idx & 31) << 2;
        pb[l] = *reinterpret_cast<const float4*>(&W[(long)kr * N + bn + cb]);
    }
    #pragma unroll
    for (int l = 0; l < 4; l++) {
        int idx = tid + l * 256;
        int r = idx >> 3, c4 = (idx & 7) << 2;
        float4 v = pa[l];
        v.x = to_tf32(v.x); v.y = to_tf32(v.y); v.z = to_tf32(v.z); v.w = to_tf32(v.w);
        *reinterpret_cast<float4*>(&As[0][r * AS_STRIDE + c4]) = v;
        int kr = idx >> 5, cb = (idx & 31) << 2;
        float4 u = pb[l];
        u.x = to_tf32(u.x); u.y = to_tf32(u.y); u.z = to_tf32(u.z); u.w = to_tf32(u.w);
        *reinterpret_cast<float4*>(&Bs[0][kr * BS_STRIDE + cb]) = u;
    }
    __syncthreads();

    int buf = 0;
    for (int k0 = 0; k0 < K; k0 += BK) {
        const bool more = (k0 + BK < K);
        if (more) {
            #pragma unroll
            for (int l = 0; l < 4; l++) {
                int idx = tid + l * 256;
                int r = idx >> 3, c4 = (idx & 7) << 2;
                pa[l] = *reinterpret_cast<const float4*>(&A[(long)(bm + r) * K + k0 + BK + c4]);
                int kr = idx >> 5, cb = (idx & 31) << 2;
                pb[l] = *reinterpret_cast<const float4*>(&W[(long)(k0 + BK + kr) * N + bn + cb]);
            }
        }

        const float* Ab = As[buf];
        const float* Bb = Bs[buf];
        #pragma unroll
        for (int ks = 0; ks < BK; ks += 8) {
            unsigned a[4][4], b[4][2];
            #pragma unroll
            for (int mt = 0; mt < 4; mt++) {
                int row = wm * 64 + mt * 16 + lq;
                a[mt][0] = __float_as_uint(Ab[row * AS_STRIDE + ks + lr]);
                a[mt][1] = __float_as_uint(Ab[(row + 8) * AS_STRIDE + ks + lr]);
                a[mt][2] = __float_as_uint(Ab[row * AS_STRIDE + ks + lr + 4]);
                a[mt][3] = __float_as_uint(Ab[(row + 8) * AS_STRIDE + ks + lr + 4]);
            }
            #pragma unroll
            for (int nt = 0; nt < 4; nt++) {
                int col = wn * 32 + nt * 8 + lq;
                b[nt][0] = __float_as_uint(Bb[(ks + lr) * BS_STRIDE + col]);
                b[nt][1] = __float_as_uint(Bb[(ks + lr + 4) * BS_STRIDE + col]);
            }
            #pragma unroll
            for (int mt = 0; mt < 4; mt++)
                #pragma unroll
                for (int nt = 0; nt < 4; nt++)
                    mma_tf32(acc[mt][nt], a[mt], b[nt]);
        }

        if (more) {
            #pragma unroll
            for (int l = 0; l < 4; l++) {
                int idx = tid + l * 256;
                int r = idx >> 3, c4 = (idx & 7) << 2;
                float4 v = pa[l];
                v.x = to_tf32(v.x); v.y = to_tf32(v.y); v.z = to_tf32(v.z); v.w = to_tf32(v.w);
                *reinterpret_cast<float4*>(&As[buf ^ 1][r * AS_STRIDE + c4]) = v;
                int kr = idx >> 5, cb = (idx & 31) << 2;
                float4 u = pb[l];
                u.x = to_tf32(u.x); u.y = to_tf32(u.y); u.z = to_tf32(u.z); u.w = to_tf32(u.w);
                *reinterpret_cast<float4*>(&Bs[buf ^ 1][kr * BS_STRIDE + cb]) = u;
            }
        }
        __syncthreads();
        buf ^= 1;
    }

    #pragma unroll
    for (int mt = 0; mt < 4; mt++) {
        int row = bm + wm * 64 + mt * 16 + lq;
        #pragma unroll
        for (int nt = 0; nt < 4; nt++) {
            int col = bn + wn * 32 + nt * 8 + 2 * lr;
            float2 v0 = make_float2(acc[mt][nt][0], acc[mt][nt][1]);
            float2 v1 = make_float2(acc[mt][nt][2], acc[mt][nt][3]);
            *reinterpret_cast<float2*>(&C[(long)row * N + col]) = v0;
            *reinterpret_cast<float2*>(&C[(long)(row + 8) * N + col]) = v1;
        }
    }
}

// ---------------------------------------------------------------------------
// RoPE (in-place)
// ---------------------------------------------------------------------------
__global__ void rope_kernel(float* __restrict__ q, int nheads)
{
    long idx = (long)blockIdx.x * blockDim.x + threadIdx.x;
    int i = (int)(idx & 63);
    long t = idx >> 6;
    int h = (int)(t % nheads);
    long row = t / nheads;
    int s = (int)(row % S_);

    float inv = powf(10000.0f, -((float)(2*i)) / (float)HD_);
    float ang = (float)s * inv;
    float sn, cs;
    sincosf(ang, &sn, &cs);

    float* p = q + row * ((long)nheads * HD_) + (long)h * HD_;
    float x1 = p[i];
    float x2 = p[i + 64];
    p[i]      = x1 * cs - x2 * sn;
    p[i + 64] = x2 * cs + x1 * sn;
}

// ---------------------------------------------------------------------------
// Tensor-core flash attention (tf32 MMA), causal.
// Grid (S/128, H, B), 256 threads (8 warps), each warp: 16 q-rows.
// Q tile 128x128 (smem), KV tiles 64x128 per iteration.
// Softmax in base-2 domain (Q pre-scaled by log2e/sqrt(HD)), ex2.approx.
// ---------------------------------------------------------------------------
#define AT_S 132      // Q/K/V smem row stride (floats)
#define AT_PS 68      // P smem row stride
#define ATTN_SMEM_FLOATS (128*AT_S + 64*AT_S + 64*AT_S + 128*AT_PS)
#define ATTN_SMEM_BYTES (ATTN_SMEM_FLOATS * 4)

__device__ __forceinline__ float red_max4(float v) {
    v = fmaxf(v, __shfl_xor_sync(0xffffffffu, v, 1));
    v = fmaxf(v, __shfl_xor_sync(0xffffffffu, v, 2));
    return v;
}
__device__ __forceinline__ float red_sum4(float v) {
    v += __shfl_xor_sync(0xffffffffu, v, 1);
    v += __shfl_xor_sync(0xffffffffu, v, 2);
    return v;
}

__global__ __launch_bounds__(256) void attn_mma_kernel()
{
    extern __shared__ float sm[];
    float* Qs = sm;                       // [128][AT_S]
    float* Ks = Qs + 128 * AT_S;          // [64][AT_S]
    float* Vs = Ks + 64 * AT_S;           // [64][AT_S]
    float* Ps = Vs + 64 * AT_S;           // [128][AT_PS]

    const int qt = blockIdx.x;            // 128-row q tile
    const int h  = blockIdx.y;
    const int b  = blockIdx.z;
    const int kvh = h / REP_;

    const int tid  = threadIdx.x;
    const int lane = tid & 31;
    const int w    = tid >> 5;
    const int lq   = lane >> 2;
    const int lr   = lane & 3;

    const float qscale = 0.08838834764831845f * 1.4426950408889634f; // log2e/sqrt(HD)

    // ---- load Q tile 128x128 (scaled, tf32) ----
    for (int i = tid; i < 128 * 32; i += 256) {
        int r = i >> 5, c4 = (i & 31) << 2;
        float4 v = *reinterpret_cast<const float4*>(
            &g_qproj[((long)(b * S_) + qt * 128 + r) * (H_ * HD_) + h * HD_ + c4]);
        v.x = to_tf32(v.x * qscale); v.y = to_tf32(v.y * qscale);
        v.z = to_tf32(v.z * qscale); v.w = to_tf32(v.w * qscale);
        *reinterpret_cast<float4*>(&Qs[r * AT_S + c4]) = v;
    }

    float o[16][4];
    #pragma unroll
    for (int nt = 0; nt < 16; nt++)
        #pragma unroll
        for (int j = 0; j < 4; j++) o[nt][j] = 0.f;
    float m0 = -1e30f, m1 = -1e30f, l0 = 0.f, l1 = 0.f;

    const int qrow = w * 16 + lq;        // warp-local q row (and +8)
    const int nkt = 2 * qt + 2;

    for (int kt = 0; kt < nkt; kt++) {
        __syncthreads();
        // ---- load K,V tiles 64x128 (tf32) ----
        for (int i = tid; i < 64 * 32; i += 256) {
            int r = i >> 5, c4 = (i & 31) << 2;
            long row = (long)(b * S_) + kt * 64 + r;
            float4 kv = *reinterpret_cast<const float4*>(
                &g_kproj[row * (KVH_ * HD_) + kvh * HD_ + c4]);
            kv.x = to_tf32(kv.x); kv.y = to_tf32(kv.y);
            kv.z = to_tf32(kv.z); kv.w = to_tf32(kv.w);
            *reinterpret_cast<float4*>(&Ks[r * AT_S + c4]) = kv;
            float4 vv = *reinterpret_cast<const float4*>(
                &g_vproj[row * (KVH_ * HD_) + kvh * HD_ + c4]);
            vv.x = to_tf32(vv.x); vv.y = to_tf32(vv.y);
            vv.z = to_tf32(vv.z); vv.w = to_tf32(vv.w);
            *reinterpret_cast<float4*>(&Vs[r * AT_S + c4]) = vv;
        }
        __syncthreads();

        // ---- scores: S = Q Kᵀ (16 x 64 per warp) ----
        float sacc[8][4];
        #pragma unroll
        for (int nt = 0; nt < 8; nt++)
            #pragma unroll
            for (int j = 0; j < 4; j++) sacc[nt][j] = 0.f;

        #pragma unroll
        for (int ks = 0; ks < 16; ks++) {
            int k0 = ks * 8;
            unsigned a[4];
            a[0] = __float_as_uint(Qs[qrow * AT_S + k0 + lr]);
            a[1] = __float_as_uint(Qs[(qrow + 8) * AT_S + k0 + lr]);
            a[2] = __float_as_uint(Qs[qrow * AT_S + k0 + lr + 4]);
            a[3] = __float_as_uint(Qs[(qrow + 8) * AT_S + k0 + lr + 4]);
            #pragma unroll
            for (int nt = 0; nt < 8; nt++) {
                unsigned bb[2];
                bb[0] = __float_as_uint(Ks[(nt * 8 + lq) * AT_S + k0 + lr]);
                bb[1] = __float_as_uint(Ks[(nt * 8 + lq) * AT_S + k0 + lr + 4]);
                mma_tf32(sacc[nt], a, bb);
            }
        }

        // ---- causal mask (only near-diagonal tiles) ----
        if (kt >= 2 * qt) {
            int r0 = qt * 128 + qrow;
            int r1 = r0 + 8;
            #pragma unroll
            for (int nt = 0; nt < 8; nt++) {
                int c = kt * 64 + nt * 8 + 2 * lr;
                if (c     > r0) sacc[nt][0] = -1e30f;
                if (c + 1 > r0) sacc[nt][1] = -1e30f;
                if (c     > r1) sacc[nt][2] = -1e30f;
                if (c + 1 > r1) sacc[nt][3] = -1e30f;
            }
        }

        // ---- online softmax (base-2) ----
        float mt0 = -1e30f, mt1 = -1e30f;
        #pragma unroll
        for (int nt = 0; nt < 8; nt++) {
            mt0 = fmaxf(mt0, fmaxf(sacc[nt][0], sacc[nt][1]));
            mt1 = fmaxf(mt1, fmaxf(sacc[nt][2], sacc[nt][3]));
        }
        mt0 = red_max4(mt0);
        mt1 = red_max4(mt1);
        float mn0 = fmaxf(m0, mt0), mn1 = fmaxf(m1, mt1);
        float alpha0 = ex2f(m0 - mn0), alpha1 = ex2f(m1 - mn1);

        float rs0 = 0.f, rs1 = 0.f;
        #pragma unroll
        for (int nt = 0; nt < 8; nt++) {
            sacc[nt][0] = ex2f(sacc[nt][0] - mn0);
            sacc[nt][1] = ex2f(sacc[nt][1] - mn0);
            sacc[nt][2] = ex2f(sacc[nt][2] - mn1);
            sacc[nt][3] = ex2f(sacc[nt][3] - mn1);
            rs0 += sacc[nt][0] + sacc[nt][1];
            rs1 += sacc[nt][2] + sacc[nt][3];
        }
        rs0 = red_sum4(rs0);
        rs1 = red_sum4(rs1);
        l0 = l0 * alpha0 + rs0;
        l1 = l1 * alpha1 + rs1;
        m0 = mn0; m1 = mn1;

        #pragma unroll
        for (int nt = 0; nt < 16; nt++) {
            o[nt][0] *= alpha0; o[nt][1] *= alpha0;
            o[nt][2] *= alpha1; o[nt][3] *= alpha1;
        }

        // ---- store P (tf32) to smem, reshape for A operand ----
        #pragma unroll
        for (int nt = 0; nt < 8; nt++) {
            *reinterpret_cast<float2*>(&Ps[qrow * AT_PS + nt * 8 + 2 * lr]) =
                make_float2(to_tf32(sacc[nt][0]), to_tf32(sacc[nt][1]));
            *reinterpret_cast<float2*>(&Ps[(qrow + 8) * AT_PS + nt * 8 + 2 * lr]) =
                make_float2(to_tf32(sacc[nt][2]), to_tf32(sacc[nt][3]));
        }
        __syncwarp();

        // ---- O += P V  (16 x 128 per warp) ----
        #pragma unroll
        for (int ks = 0; ks < 8; ks++) {
            int k0 = ks * 8;
            unsigned a[4];
            a[0] = __float_as_uint(Ps[qrow * AT_PS + k0 + lr]);
            a[1] = __float_as_uint(Ps[(qrow + 8) * AT_PS + k0 + lr]);
            a[2] = __float_as_uint(Ps[qrow * AT_PS + k0 + lr + 4]);
            a[3] = __float_as_uint(Ps[(qrow + 8) * AT_PS + k0 + lr + 4]);
            #pragma unroll
            for (int nt = 0; nt < 16; nt++) {
                unsigned bb[2];
                bb[0] = __float_as_uint(Vs[(k0 + lr) * AT_S + nt * 8 + lq]);
                bb[1] = __float_as_uint(Vs[(k0 + lr + 4) * AT_S + nt * 8 + lq]);
                mma_tf32(o[nt], a, bb);
            }
        }
    }

    // ---- epilogue: normalize and write ----
    float inv0 = 1.0f / l0;
    float inv1 = 1.0f / l1;
    long base0 = ((long)(b * S_) + qt * 128 + qrow) * (H_ * HD_) + h * HD_;
    long base1 = base0 + (long)8 * (H_ * HD_);
    #pragma unroll
    for (int nt = 0; nt < 16; nt++) {
        int c = nt * 8 + 2 * lr;
        *reinterpret_cast<float2*>(&g_attn[base0 + c]) =
            make_float2(o[nt][0] * inv0, o[nt][1] * inv0);
        *reinterpret_cast<float2*>(&g_attn[base1 + c]) =
            make_float2(o[nt][2] * inv1, o[nt][3] * inv1);
    }
}

// ---------------------------------------------------------------------------
extern "C" void kernel_launch(void* const* d_in, const int* in_sizes, int n_in,
                              void* d_out, int out_size)
{
    const float* x  = (const float*)d_in[0];
    const float* Wq = (const float*)d_in[1];
    const float* Wk = (const float*)d_in[2];
    const float* Wv = (const float*)d_in[3];
    const float* Wo = (const float*)d_in[4];
    float* out = (float*)d_out;

    float *qproj, *kproj, *vproj, *attn;
    cudaGetSymbolAddress((void**)&qproj, g_qproj);
    cudaGetSymbolAddress((void**)&kproj, g_kproj);
    cudaGetSymbolAddress((void**)&vproj, g_vproj);
    cudaGetSymbolAddress((void**)&attn,  g_attn);

    const int M = B_ * S_;   // 4096

    tf32_gemm_kernel<<<dim3((H_*HD_)/BN,   M/BM), 256>>>(x, Wq, qproj, M, H_*HD_,   D_);
    tf32_gemm_kernel<<<dim3((KVH_*HD_)/BN, M/BM), 256>>>(x, Wk, kproj, M, KVH_*HD_, D_);
    tf32_gemm_kernel<<<dim3((KVH_*HD_)/BN, M/BM), 256>>>(x, Wv, vproj, M, KVH_*HD_, D_);

    rope_kernel<<<(B_*S_*H_*64)/256,   256>>>(qproj, H_);
    rope_kernel<<<(B_*S_*KVH_*64)/256, 256>>>(kproj, KVH_);

    cudaFuncSetAttribute(attn_mma_kernel,
                         cudaFuncAttributeMaxDynamicSharedMemorySize, ATTN_SMEM_BYTES);
    attn_mma_kernel<<<dim3(S_/128, H_, B_), 256, ATTN_SMEM_BYTES>>>();

    tf32_gemm_kernel<<<dim3(D_/BN, M/BM), 256>>>(attn, Wo, out, M, D_, D_);
}

// round 5
// speedup vs baseline: 3.2224x; 1.0836x over previous
#include <cuda_runtime.h>
#include <math.h>

#define B_ 2
#define S_ 2048
#define D_ 2048
#define H_ 16
#define KVH_ 4
#define HD_ 128
#define REP_ (H_/KVH_)

// Scratch (device globals: allocation-free)
__device__ float g_qproj[B_*S_*H_*HD_];
__device__ float g_kproj[B_*S_*KVH_*HD_];
__device__ float g_vproj[B_*S_*KVH_*HD_];
__device__ float g_attn [B_*S_*H_*HD_];
// tf32-rounded operand copies
__device__ float g_xr [B_*S_*D_];
__device__ float g_wqr[D_*H_*HD_];
__device__ float g_wkr[D_*KVH_*HD_];
__device__ float g_wvr[D_*KVH_*HD_];
__device__ float g_wor[H_*HD_*D_];

__device__ __forceinline__ float to_tf32(float x) {
    float r;
    asm("cvt.rna.tf32.f32 %0, %1;" : "=f"(r) : "f"(x));
    return r;
}
__device__ __forceinline__ float ex2f(float x) {
    float r;
    asm("ex2.approx.ftz.f32 %0, %1;" : "=f"(r) : "f"(x));
    return r;
}
__device__ __forceinline__ void mma_tf32(
    float* c, const unsigned* a, const unsigned* b)
{
    asm volatile(
        "mma.sync.aligned.m16n8k8.row.col.f32.tf32.tf32.f32 "
        "{%0,%1,%2,%3}, {%4,%5,%6,%7}, {%8,%9}, {%0,%1,%2,%3};"
        : "+f"(c[0]), "+f"(c[1]), "+f"(c[2]), "+f"(c[3])
        : "r"(a[0]), "r"(a[1]), "r"(a[2]), "r"(a[3]),
          "r"(b[0]), "r"(b[1]));
}
__device__ __forceinline__ void cp16(void* s, const void* g) {
    unsigned sa = (unsigned)__cvta_generic_to_shared(s);
    asm volatile("cp.async.cg.shared.global [%0], [%1], 16;" :: "r"(sa), "l"(g));
}
#define CP_COMMIT()  asm volatile("cp.async.commit_group;")
#define CP_WAIT(n)   asm volatile("cp.async.wait_group %0;" :: "n"(n))

// ---------------------------------------------------------------------------
// Elementwise tf32 rounding pass
// ---------------------------------------------------------------------------
__global__ void round_tf32_kernel(const float* __restrict__ in,
                                  float* __restrict__ out, int n4)
{
    int i = blockIdx.x * blockDim.x + threadIdx.x;
    if (i < n4) {
        float4 v = reinterpret_cast<const float4*>(in)[i];
        v.x = to_tf32(v.x); v.y = to_tf32(v.y);
        v.z = to_tf32(v.z); v.w = to_tf32(v.w);
        reinterpret_cast<float4*>(out)[i] = v;
    }
}

// ---------------------------------------------------------------------------
// TF32 GEMM, cp.async 3-stage pipeline. Operands must be pre-rounded tf32.
// BM=128, BN=128, BK=32, 256 threads (8 warps 2x4), warp tile 64x32.
// ---------------------------------------------------------------------------
#define BM 128
#define BN 128
#define BK 32
#define AS_STRIDE 36
#define BS_STRIDE 136
#define GEMM_SMEM_BYTES (3 * (BM*AS_STRIDE + BK*BS_STRIDE) * 4)

template<bool ROUND>
__global__ __launch_bounds__(256) void gemm_pipe_kernel(
    const float* __restrict__ A, const float* __restrict__ W,
    float* __restrict__ C, int M, int N, int K)
{
    extern __shared__ float sm[];
    float* AsBase = sm;                          // 3 x BM*AS_STRIDE
    float* BsBase = sm + 3 * BM * AS_STRIDE;     // 3 x BK*BS_STRIDE

    const int tid  = threadIdx.x;
    const int lane = tid & 31;
    const int warp = tid >> 5;
    const int wm   = warp >> 2;
    const int wn   = warp & 3;
    const int bm   = blockIdx.y * BM;
    const int bn   = blockIdx.x * BN;
    const int lq = lane >> 2;
    const int lr = lane & 3;

    float acc[4][4][4];
    #pragma unroll
    for (int mt = 0; mt < 4; mt++)
        #pragma unroll
        for (int nt = 0; nt < 4; nt++)
            #pragma unroll
            for (int i = 0; i < 4; i++) acc[mt][nt][i] = 0.f;

    const int nIter = K / BK;

    auto issue = [&](int k0, int s) {
        float* As = AsBase + s * BM * AS_STRIDE;
        float* Bs = BsBase + s * BK * BS_STRIDE;
        #pragma unroll
        for (int l = 0; l < 4; l++) {
            int idx = tid + l * 256;
            int r = idx >> 3, c4 = (idx & 7) << 2;
            cp16(&As[r * AS_STRIDE + c4], &A[(long)(bm + r) * K + k0 + c4]);
            int kr = idx >> 5, cb = (idx & 31) << 2;
            cp16(&Bs[kr * BS_STRIDE + cb], &W[(long)(k0 + kr) * N + bn + cb]);
        }
        CP_COMMIT();
    };

    issue(0, 0);
    issue(BK, 1);

    for (int it = 0; it < nIter; it++) {
        if (it + 1 < nIter) { CP_WAIT(1); } else { CP_WAIT(0); }
        __syncthreads();
        if (it + 2 < nIter) issue((it + 2) * BK, (it + 2) % 3);

        const float* Ab = AsBase + (it % 3) * BM * AS_STRIDE;
        const float* Bb = BsBase + (it % 3) * BK * BS_STRIDE;
        #pragma unroll
        for (int ks = 0; ks < BK; ks += 8) {
            unsigned a[4][4], b[4][2];
            #pragma unroll
            for (int mt = 0; mt < 4; mt++) {
                int row = wm * 64 + mt * 16 + lq;
                a[mt][0] = __float_as_uint(Ab[row * AS_STRIDE + ks + lr]);
                a[mt][1] = __float_as_uint(Ab[(row + 8) * AS_STRIDE + ks + lr]);
                a[mt][2] = __float_as_uint(Ab[row * AS_STRIDE + ks + lr + 4]);
                a[mt][3] = __float_as_uint(Ab[(row + 8) * AS_STRIDE + ks + lr + 4]);
            }
            #pragma unroll
            for (int nt = 0; nt < 4; nt++) {
                int col = wn * 32 + nt * 8 + lq;
                b[nt][0] = __float_as_uint(Bb[(ks + lr) * BS_STRIDE + col]);
                b[nt][1] = __float_as_uint(Bb[(ks + lr + 4) * BS_STRIDE + col]);
            }
            #pragma unroll
            for (int mt = 0; mt < 4; mt++)
                #pragma unroll
                for (int nt = 0; nt < 4; nt++)
                    mma_tf32(acc[mt][nt], a[mt], b[nt]);
        }
        __syncthreads();
    }

    #pragma unroll
    for (int mt = 0; mt < 4; mt++) {
        int row = bm + wm * 64 + mt * 16 + lq;
        #pragma unroll
        for (int nt = 0; nt < 4; nt++) {
            int col = bn + wn * 32 + nt * 8 + 2 * lr;
            float2 v0, v1;
            if (ROUND) {
                v0 = make_float2(to_tf32(acc[mt][nt][0]), to_tf32(acc[mt][nt][1]));
                v1 = make_float2(to_tf32(acc[mt][nt][2]), to_tf32(acc[mt][nt][3]));
            } else {
                v0 = make_float2(acc[mt][nt][0], acc[mt][nt][1]);
                v1 = make_float2(acc[mt][nt][2], acc[mt][nt][3]);
            }
            *reinterpret_cast<float2*>(&C[(long)row * N + col]) = v0;
            *reinterpret_cast<float2*>(&C[(long)(row + 8) * N + col]) = v1;
        }
    }
}

// ---------------------------------------------------------------------------
// RoPE (in-place), emits tf32-rounded values.
// ---------------------------------------------------------------------------
__global__ void rope_kernel(float* __restrict__ q, int nheads)
{
    long idx = (long)blockIdx.x * blockDim.x + threadIdx.x;
    int i = (int)(idx & 63);
    long t = idx >> 6;
    int h = (int)(t % nheads);
    long row = t / nheads;
    int s = (int)(row % S_);

    float inv = powf(10000.0f, -((float)(2*i)) / (float)HD_);
    float ang = (float)s * inv;
    float sn, cs;
    sincosf(ang, &sn, &cs);

    float* p = q + row * ((long)nheads * HD_) + (long)h * HD_;
    float x1 = p[i];
    float x2 = p[i + 64];
    p[i]      = to_tf32(x1 * cs - x2 * sn);
    p[i + 64] = to_tf32(x2 * cs + x1 * sn);
}

// ---------------------------------------------------------------------------
// Tensor-core flash attention, cp.async pipelined, causal.
// Grid (S/128, H, B), 256 threads (8 warps), warp = 16 q rows.
// K double-buffered, V single-buffered. Inputs pre-rounded tf32.
// Scores scaled AFTER the QK mma (scale folded with log2e).
// ---------------------------------------------------------------------------
#define AT_S 132
#define AT_PS 68
#define ATTN_SMEM_FLOATS (128*AT_S + 2*64*AT_S + 64*AT_S + 128*AT_PS)
#define ATTN_SMEM_BYTES (ATTN_SMEM_FLOATS * 4)

__device__ __forceinline__ float red_max4(float v) {
    v = fmaxf(v, __shfl_xor_sync(0xffffffffu, v, 1));
    v = fmaxf(v, __shfl_xor_sync(0xffffffffu, v, 2));
    return v;
}
__device__ __forceinline__ float red_sum4(float v) {
    v += __shfl_xor_sync(0xffffffffu, v, 1);
    v += __shfl_xor_sync(0xffffffffu, v, 2);
    return v;
}

__global__ __launch_bounds__(256) void attn_mma_kernel()
{
    extern __shared__ float sm[];
    float* Qs  = sm;                            // [128][AT_S]
    float* Ks0 = Qs + 128 * AT_S;               // [64][AT_S] x2
    float* Vs  = Ks0 + 2 * 64 * AT_S;           // [64][AT_S]
    float* Ps  = Vs + 64 * AT_S;                // [128][AT_PS]

    const int qt = (int)(gridDim.x - 1) - blockIdx.x;  // big tiles first
    const int h  = blockIdx.y;
    const int b  = blockIdx.z;
    const int kvh = h / REP_;

    const int tid  = threadIdx.x;
    const int lane = tid & 31;
    const int w    = tid >> 5;
    const int lq   = lane >> 2;
    const int lr   = lane & 3;

    const float SCL = 0.08838834764831845f * 1.4426950408889634f; // log2e/sqrt(HD)

    const int nkt = 2 * qt + 2;

    // ---- prologue: Q tile + K tile 0 (one commit group) ----
    #pragma unroll
    for (int l = 0; l < 16; l++) {
        int i = tid + l * 256;
        int r = i >> 5, c4 = (i & 31) << 2;
        cp16(&Qs[r * AT_S + c4],
             &g_qproj[((long)(b * S_) + qt * 128 + r) * (H_ * HD_) + h * HD_ + c4]);
    }
    #pragma unroll
    for (int l = 0; l < 8; l++) {
        int i = tid + l * 256;
        int r = i >> 5, c4 = (i & 31) << 2;
        cp16(&Ks0[r * AT_S + c4],
             &g_kproj[((long)(b * S_) + r) * (KVH_ * HD_) + kvh * HD_ + c4]);
    }
    CP_COMMIT();

    float o[16][4];
    #pragma unroll
    for (int nt = 0; nt < 16; nt++)
        #pragma unroll
        for (int j = 0; j < 4; j++) o[nt][j] = 0.f;
    float m0 = -1e30f, m1 = -1e30f, l0 = 0.f, l1 = 0.f;

    const int qrow = w * 16 + lq;

    for (int kt = 0; kt < nkt; kt++) {
        __syncthreads();   // V/P buffers free of previous-iter readers

        // issue V(kt)
        #pragma unroll
        for (int l = 0; l < 8; l++) {
            int i = tid + l * 256;
            int r = i >> 5, c4 = (i & 31) << 2;
            cp16(&Vs[r * AT_S + c4],
                 &g_vproj[((long)(b * S_) + kt * 64 + r) * (KVH_ * HD_) + kvh * HD_ + c4]);
        }
        CP_COMMIT();
        // issue K(kt+1)
        if (kt + 1 < nkt) {
            float* Kn = Ks0 + ((kt + 1) & 1) * 64 * AT_S;
            #pragma unroll
            for (int l = 0; l < 8; l++) {
                int i = tid + l * 256;
                int r = i >> 5, c4 = (i & 31) << 2;
                cp16(&Kn[r * AT_S + c4],
                     &g_kproj[((long)(b * S_) + (kt + 1) * 64 + r) * (KVH_ * HD_) + kvh * HD_ + c4]);
            }
            CP_COMMIT();
        }

        // wait for K(kt) (+Q)
        if (kt + 1 < nkt) { CP_WAIT(2); } else { CP_WAIT(1); }
        __syncthreads();

        const float* Kb = Ks0 + (kt & 1) * 64 * AT_S;

        // ---- scores: S = Q Kᵀ ----
        float sacc[8][4];
        #pragma unroll
        for (int nt = 0; nt < 8; nt++)
            #pragma unroll
            for (int j = 0; j < 4; j++) sacc[nt][j] = 0.f;

        #pragma unroll
        for (int ks = 0; ks < 16; ks++) {
            int k0 = ks * 8;
            unsigned a[4];
            a[0] = __float_as_uint(Qs[qrow * AT_S + k0 + lr]);
            a[1] = __float_as_uint(Qs[(qrow + 8) * AT_S + k0 + lr]);
            a[2] = __float_as_uint(Qs[qrow * AT_S + k0 + lr + 4]);
            a[3] = __float_as_uint(Qs[(qrow + 8) * AT_S + k0 + lr + 4]);
            #pragma unroll
            for (int nt = 0; nt < 8; nt++) {
                unsigned bb[2];
                bb[0] = __float_as_uint(Kb[(nt * 8 + lq) * AT_S + k0 + lr]);
                bb[1] = __float_as_uint(Kb[(nt * 8 + lq) * AT_S + k0 + lr + 4]);
                mma_tf32(sacc[nt], a, bb);
            }
        }

        // scale (post-mma), then causal mask
        #pragma unroll
        for (int nt = 0; nt < 8; nt++)
            #pragma unroll
            for (int j = 0; j < 4; j++) sacc[nt][j] *= SCL;

        if (kt >= 2 * qt) {
            int r0 = qt * 128 + qrow;
            int r1 = r0 + 8;
            #pragma unroll
            for (int nt = 0; nt < 8; nt++) {
                int c = kt * 64 + nt * 8 + 2 * lr;
                if (c     > r0) sacc[nt][0] = -1e30f;
                if (c + 1 > r0) sacc[nt][1] = -1e30f;
                if (c     > r1) sacc[nt][2] = -1e30f;
                if (c + 1 > r1) sacc[nt][3] = -1e30f;
            }
        }

        // ---- online softmax (base-2) ----
        float mt0 = -1e30f, mt1 = -1e30f;
        #pragma unroll
        for (int nt = 0; nt < 8; nt++) {
            mt0 = fmaxf(mt0, fmaxf(sacc[nt][0], sacc[nt][1]));
            mt1 = fmaxf(mt1, fmaxf(sacc[nt][2], sacc[nt][3]));
        }
        mt0 = red_max4(mt0);
        mt1 = red_max4(mt1);
        float mn0 = fmaxf(m0, mt0), mn1 = fmaxf(m1, mt1);
        float alpha0 = ex2f(m0 - mn0), alpha1 = ex2f(m1 - mn1);

        float rs0 = 0.f, rs1 = 0.f;
        #pragma unroll
        for (int nt = 0; nt < 8; nt++) {
            sacc[nt][0] = ex2f(sacc[nt][0] - mn0);
            sacc[nt][1] = ex2f(sacc[nt][1] - mn0);
            sacc[nt][2] = ex2f(sacc[nt][2] - mn1);
            sacc[nt][3] = ex2f(sacc[nt][3] - mn1);
            rs0 += sacc[nt][0] + sacc[nt][1];
            rs1 += sacc[nt][2] + sacc[nt][3];
        }
        rs0 = red_sum4(rs0);
        rs1 = red_sum4(rs1);
        l0 = l0 * alpha0 + rs0;
        l1 = l1 * alpha1 + rs1;
        m0 = mn0; m1 = mn1;

        #pragma unroll
        for (int nt = 0; nt < 16; nt++) {
            o[nt][0] *= alpha0; o[nt][1] *= alpha0;
            o[nt][2] *= alpha1; o[nt][3] *= alpha1;
        }

        // ---- store P (tf32) ----
        #pragma unroll
        for (int nt = 0; nt < 8; nt++) {
            *reinterpret_cast<float2*>(&Ps[qrow * AT_PS + nt * 8 + 2 * lr]) =
                make_float2(to_tf32(sacc[nt][0]), to_tf32(sacc[nt][1]));
            *reinterpret_cast<float2*>(&Ps[(qrow + 8) * AT_PS + nt * 8 + 2 * lr]) =
                make_float2(to_tf32(sacc[nt][2]), to_tf32(sacc[nt][3]));
        }

        // wait for V(kt)
        if (kt + 1 < nkt) { CP_WAIT(1); } else { CP_WAIT(0); }
        __syncthreads();

        // ---- O += P V ----
        #pragma unroll
        for (int ks = 0; ks < 8; ks++) {
            int k0 = ks * 8;
            unsigned a[4];
            a[0] = __float_as_uint(Ps[qrow * AT_PS + k0 + lr]);
            a[1] = __float_as_uint(Ps[(qrow + 8) * AT_PS + k0 + lr]);
            a[2] = __float_as_uint(Ps[qrow * AT_PS + k0 + lr + 4]);
            a[3] = __float_as_uint(Ps[(qrow + 8) * AT_PS + k0 + lr + 4]);
            #pragma unroll
            for (int nt = 0; nt < 16; nt++) {
                unsigned bb[2];
                bb[0] = __float_as_uint(Vs[(k0 + lr) * AT_S + nt * 8 + lq]);
                bb[1] = __float_as_uint(Vs[(k0 + lr + 4) * AT_S + nt * 8 + lq]);
                mma_tf32(o[nt], a, bb);
            }
        }
    }

    // ---- epilogue: normalize, round to tf32 (feeds O-projection), write ----
    float inv0 = 1.0f / l0;
    float inv1 = 1.0f / l1;
    long base0 = ((long)(b * S_) + qt * 128 + qrow) * (H_ * HD_) + h * HD_;
    long base1 = base0 + (long)8 * (H_ * HD_);
    #pragma unroll
    for (int nt = 0; nt < 16; nt++) {
        int c = nt * 8 + 2 * lr;
        *reinterpret_cast<float2*>(&g_attn[base0 + c]) =
            make_float2(to_tf32(o[nt][0] * inv0), to_tf32(o[nt][1] * inv0));
        *reinterpret_cast<float2*>(&g_attn[base1 + c]) =
            make_float2(to_tf32(o[nt][2] * inv1), to_tf32(o[nt][3] * inv1));
    }
}

// ---------------------------------------------------------------------------
extern "C" void kernel_launch(void* const* d_in, const int* in_sizes, int n_in,
                              void* d_out, int out_size)
{
    const float* x  = (const float*)d_in[0];
    const float* Wq = (const float*)d_in[1];
    const float* Wk = (const float*)d_in[2];
    const float* Wv = (const float*)d_in[3];
    const float* Wo = (const float*)d_in[4];
    float* out = (float*)d_out;

    float *qproj, *kproj, *vproj, *attn;
    float *xr, *wqr, *wkr, *wvr, *wor;
    cudaGetSymbolAddress((void**)&qproj, g_qproj);
    cudaGetSymbolAddress((void**)&kproj, g_kproj);
    cudaGetSymbolAddress((void**)&vproj, g_vproj);
    cudaGetSymbolAddress((void**)&attn,  g_attn);
    cudaGetSymbolAddress((void**)&xr,  g_xr);
    cudaGetSymbolAddress((void**)&wqr, g_wqr);
    cudaGetSymbolAddress((void**)&wkr, g_wkr);
    cudaGetSymbolAddress((void**)&wvr, g_wvr);
    cudaGetSymbolAddress((void**)&wor, g_wor);

    const int M = B_ * S_;   // 4096

    // tf32 rounding passes
    round_tf32_kernel<<<(B_*S_*D_/4 + 255)/256, 256>>>(x,  xr,  B_*S_*D_/4);
    round_tf32_kernel<<<(D_*H_*HD_/4 + 255)/256, 256>>>(Wq, wqr, D_*H_*HD_/4);
    round_tf32_kernel<<<(D_*KVH_*HD_/4 + 255)/256, 256>>>(Wk, wkr, D_*KVH_*HD_/4);
    round_tf32_kernel<<<(D_*KVH_*HD_/4 + 255)/256, 256>>>(Wv, wvr, D_*KVH_*HD_/4);
    round_tf32_kernel<<<(H_*HD_*D_/4 + 255)/256, 256>>>(Wo, wor, H_*HD_*D_/4);

    cudaFuncSetAttribute(gemm_pipe_kernel<true>,
                         cudaFuncAttributeMaxDynamicSharedMemorySize, GEMM_SMEM_BYTES);
    cudaFuncSetAttribute(gemm_pipe_kernel<false>,
                         cudaFuncAttributeMaxDynamicSharedMemorySize, GEMM_SMEM_BYTES);

    // QKV projections (outputs tf32-rounded)
    gemm_pipe_kernel<true><<<dim3((H_*HD_)/BN,   M/BM), 256, GEMM_SMEM_BYTES>>>(
        xr, wqr, qproj, M, H_*HD_,   D_);
    gemm_pipe_kernel<true><<<dim3((KVH_*HD_)/BN, M/BM), 256, GEMM_SMEM_BYTES>>>(
        xr, wkr, kproj, M, KVH_*HD_, D_);
    gemm_pipe_kernel<true><<<dim3((KVH_*HD_)/BN, M/BM), 256, GEMM_SMEM_BYTES>>>(
        xr, wvr, vproj, M, KVH_*HD_, D_);

    // RoPE in-place (rounds outputs)
    rope_kernel<<<(B_*S_*H_*64)/256,   256>>>(qproj, H_);
    rope_kernel<<<(B_*S_*KVH_*64)/256, 256>>>(kproj, KVH_);

    // Flash attention
    cudaFuncSetAttribute(attn_mma_kernel,
                         cudaFuncAttributeMaxDynamicSharedMemorySize, ATTN_SMEM_BYTES);
    attn_mma_kernel<<<dim3(S_/128, H_, B_), 256, ATTN_SMEM_BYTES>>>();

    // Output projection (unrounded output)
    gemm_pipe_kernel<false><<<dim3(D_/BN, M/BM), 256, GEMM_SMEM_BYTES>>>(
        attn, wor, out, M, D_, D_);
}

// round 9
// speedup vs baseline: 7.0329x; 2.1825x over previous
#include <cuda_runtime.h>
#include <cuda_fp16.h>
#include <math.h>
#include <stdint.h>

#define B_ 2
#define S_ 2048
#define D_ 2048
#define H_ 16
#define KVH_ 4
#define HD_ 128
#define REP_ (H_/KVH_)

// Scratch (device globals: allocation-free), all fp16 operands
__device__ __half g_xh   [B_*S_*D_];
__device__ __half g_wqh  [D_*H_*HD_];      // [N,K]
__device__ __half g_wkh  [D_*KVH_*HD_];    // [N,K]
__device__ __half g_wvh  [D_*KVH_*HD_];    // [N,K]
__device__ __half g_woh  [H_*HD_*D_];      // [N,K] = [D, H*HD]
__device__ __half g_qproj[B_*S_*H_*HD_];
__device__ __half g_kproj[B_*S_*KVH_*HD_];
__device__ __half g_vproj[B_*S_*KVH_*HD_];
__device__ __half g_attn [B_*S_*H_*HD_];

// ---------------------------------------------------------------------------
// helpers
// ---------------------------------------------------------------------------
__device__ __forceinline__ float ex2f(float x) {
    float r;
    asm("ex2.approx.ftz.f32 %0, %1;" : "=f"(r) : "f"(x));
    return r;
}
__device__ __forceinline__ void mma_f16(
    float* c, const unsigned* a, const unsigned* b)
{
    asm volatile(
        "mma.sync.aligned.m16n8k16.row.col.f32.f16.f16.f32 "
        "{%0,%1,%2,%3}, {%4,%5,%6,%7}, {%8,%9}, {%0,%1,%2,%3};"
        : "+f"(c[0]), "+f"(c[1]), "+f"(c[2]), "+f"(c[3])
        : "r"(a[0]), "r"(a[1]), "r"(a[2]), "r"(a[3]),
          "r"(b[0]), "r"(b[1]));
}
__device__ __forceinline__ void cp16(void* s, const void* g) {
    unsigned sa = (unsigned)__cvta_generic_to_shared(s);
    asm volatile("cp.async.cg.shared.global [%0], [%1], 16;" :: "r"(sa), "l"(g));
}
#define CP_COMMIT()  asm volatile("cp.async.commit_group;")
#define CP_WAIT(n)   asm volatile("cp.async.wait_group %0;" :: "n"(n))

__device__ __forceinline__ unsigned lds32(const char* p) {
    return *reinterpret_cast<const unsigned*>(p);
}
__device__ __forceinline__ void ldmatrix_x4_trans(
    unsigned& r0, unsigned& r1, unsigned& r2, unsigned& r3, unsigned addr)
{
    asm volatile(
        "ldmatrix.sync.aligned.m8n8.x4.trans.shared.b16 {%0,%1,%2,%3}, [%4];"
        : "=r"(r0), "=r"(r1), "=r"(r2), "=r"(r3) : "r"(addr));
}
__device__ __forceinline__ unsigned pack_h2(float lo, float hi) {
    __half2 h = __floats2half2_rn(lo, hi);
    return *reinterpret_cast<unsigned*>(&h);
}

// ---------------------------------------------------------------------------
// fp32 -> fp16 convert
// ---------------------------------------------------------------------------
__global__ void convert_half_kernel(const float* __restrict__ in,
                                    __half* __restrict__ out, int n4)
{
    int i = blockIdx.x * blockDim.x + threadIdx.x;
    if (i < n4) {
        float4 v = reinterpret_cast<const float4*>(in)[i];
        uint2 u;
        u.x = pack_h2(v.x, v.y);
        u.y = pack_h2(v.z, v.w);
        reinterpret_cast<uint2*>(out)[i] = u;
    }
}

// ---------------------------------------------------------------------------
// Transpose + convert: in fp32 [K,N] row-major -> out fp16 [N,K] row-major
// ---------------------------------------------------------------------------
__global__ void transpose_convert_kernel(const float* __restrict__ in,
                                         __half* __restrict__ out, int K, int N)
{
    __shared__ float t[32][33];
    int k0 = blockIdx.y * 32, n0 = blockIdx.x * 32;
    int x = threadIdx.x, y = threadIdx.y;
    #pragma unroll
    for (int i = 0; i < 32; i += 8)
        t[y + i][x] = in[(long)(k0 + y + i) * N + n0 + x];
    __syncthreads();
    #pragma unroll
    for (int i = 0; i < 32; i += 8)
        out[(long)(n0 + y + i) * K + k0 + x] = __float2half_rn(t[x][y + i]);
}

// ---------------------------------------------------------------------------
// FP16 GEMM: C[M,N] = A[M,K] @ Bt[N,K]^T, fp32 accum.
// 256 threads (8 warps 2x4), CTA tile 128x128, BK=64 halves (128B rows),
// XOR-swizzled smem, 3-stage cp.async ring, packed 32-bit fragment loads.
// ---------------------------------------------------------------------------
#define HT_BYTES (128*128)   // one operand tile: 128 rows x 128B
#define HNS 3
#define HSM_TOTAL (2*HNS*HT_BYTES)   // 98304

template<bool HOUT>
__global__ __launch_bounds__(256) void h_gemm_kernel(
    const __half* __restrict__ A, const __half* __restrict__ Bt,
    void* __restrict__ Cv, int M, int N, int K)
{
    extern __shared__ char smem[];
    char* AsBase = smem;                    // 3 x 16KB
    char* BsBase = smem + HNS * HT_BYTES;   // 3 x 16KB

    const int tid  = threadIdx.x;
    const int lane = tid & 31;
    const int warp = tid >> 5;
    const int wm   = warp >> 2;
    const int wn   = warp & 3;
    const int bm   = blockIdx.y * 128;
    const int bn   = blockIdx.x * 128;
    const int lq = lane >> 2;     // 0..7
    const int lr = lane & 3;      // 0..3

    float acc[4][4][4];
    #pragma unroll
    for (int mt = 0; mt < 4; mt++)
        #pragma unroll
        for (int nt = 0; nt < 4; nt++)
            #pragma unroll
            for (int i = 0; i < 4; i++) acc[mt][nt][i] = 0.f;

    const int NK = K >> 6;   // K/64

    // fill k-tile j into ring slot s: 128 rows x 8 16B-chunks per operand
    auto fill = [&](int j, int s) {
        char* As = AsBase + s * HT_BYTES;
        char* Bs = BsBase + s * HT_BYTES;
        const __half* Ag = A  + (long)bm * K + j * 64;
        const __half* Bg = Bt + (long)bn * K + j * 64;
        #pragma unroll
        for (int l = 0; l < 4; l++) {
            int idx = tid + l * 256;       // 0..1023
            int r = idx >> 3, c8 = idx & 7;
            int dst = r * 128 + ((c8 ^ (r & 7)) << 4);
            cp16(As + dst, Ag + (long)r * K + c8 * 8);
            cp16(Bs + dst, Bg + (long)r * K + c8 * 8);
        }
        CP_COMMIT();
    };

    fill(0, 0);
    if (NK > 1) fill(1, 1);

    for (int it = 0; it < NK; it++) {
        if (it + 1 < NK) { CP_WAIT(1); } else { CP_WAIT(0); }
        __syncthreads();
        if (it + 2 < NK) fill(it + 2, (it + 2) % 3);

        const char* Ab = AsBase + (it % 3) * HT_BYTES;
        const char* Bb = BsBase + (it % 3) * HT_BYTES;

        #pragma unroll
        for (int ks = 0; ks < 4; ks++) {
            const int c0 = (2 * ks) ^ lq;        // swizzled chunk (rows&7 == lq)
            const int c1 = (2 * ks + 1) ^ lq;
            unsigned a[4][4], b[4][2];
            #pragma unroll
            for (int mt = 0; mt < 4; mt++) {
                int row = (wm * 64 + mt * 16 + lq) * 128;
                a[mt][0] = lds32(Ab + row        + (c0 << 4) + 4 * lr);
                a[mt][1] = lds32(Ab + row + 1024 + (c0 << 4) + 4 * lr);
                a[mt][2] = lds32(Ab + row        + (c1 << 4) + 4 * lr);
                a[mt][3] = lds32(Ab + row + 1024 + (c1 << 4) + 4 * lr);
            }
            #pragma unroll
            for (int nt = 0; nt < 4; nt++) {
                int rowb = (wn * 32 + nt * 8 + lq) * 128;
                b[nt][0] = lds32(Bb + rowb + (c0 << 4) + 4 * lr);
                b[nt][1] = lds32(Bb + rowb + (c1 << 4) + 4 * lr);
            }
            #pragma unroll
            for (int mt = 0; mt < 4; mt++)
                #pragma unroll
                for (int nt = 0; nt < 4; nt++)
                    mma_f16(acc[mt][nt], a[mt], b[nt]);
        }
        __syncthreads();
    }

    // epilogue
    #pragma unroll
    for (int mt = 0; mt < 4; mt++) {
        long row0 = bm + wm * 64 + mt * 16 + lq;
        long row1 = row0 + 8;
        #pragma unroll
        for (int nt = 0; nt < 4; nt++) {
            int col = bn + wn * 32 + nt * 8 + 2 * lr;
            if (HOUT) {
                __half* C = (__half*)Cv;
                *reinterpret_cast<unsigned*>(&C[row0 * N + col]) =
                    pack_h2(acc[mt][nt][0], acc[mt][nt][1]);
                *reinterpret_cast<unsigned*>(&C[row1 * N + col]) =
                    pack_h2(acc[mt][nt][2], acc[mt][nt][3]);
            } else {
                float* C = (float*)Cv;
                *reinterpret_cast<float2*>(&C[row0 * N + col]) =
                    make_float2(acc[mt][nt][0], acc[mt][nt][1]);
                *reinterpret_cast<float2*>(&C[row1 * N + col]) =
                    make_float2(acc[mt][nt][2], acc[mt][nt][3]);
            }
        }
    }
}

// ---------------------------------------------------------------------------
// RoPE (in-place, fp16 storage, fp32 math)
// ---------------------------------------------------------------------------
__global__ void rope_half_kernel(__half* __restrict__ q, int nheads)
{
    long idx = (long)blockIdx.x * blockDim.x + threadIdx.x;
    int i = (int)(idx & 63);
    long t = idx >> 6;
    int h = (int)(t % nheads);
    long row = t / nheads;
    int s = (int)(row % S_);

    float inv = powf(10000.0f, -((float)(2*i)) / (float)HD_);
    float ang = (float)s * inv;
    float sn, cs;
    sincosf(ang, &sn, &cs);

    __half* p = q + row * ((long)nheads * HD_) + (long)h * HD_;
    float x1 = __half2float(p[i]);
    float x2 = __half2float(p[i + 64]);
    p[i]      = __float2half_rn(x1 * cs - x2 * sn);
    p[i + 64] = __float2half_rn(x2 * cs + x1 * sn);
}

// ---------------------------------------------------------------------------
// FP16 tensor-core flash attention, cp.async pipelined, causal.
// Grid (S/128, H, B), 256 threads (8 warps), warp = 16 q rows.
// Q[128][256B], K 2x[64][256B], V[64][256B] (ldmatrix.trans), P[128][128B].
// ---------------------------------------------------------------------------
#define AQ_OFF 0
#define AK_OFF 32768
#define AV_OFF 65536
#define AP_OFF 81920
#define ATTN_SMEM_BYTES 98304

__device__ __forceinline__ float red_max4(float v) {
    v = fmaxf(v, __shfl_xor_sync(0xffffffffu, v, 1));
    v = fmaxf(v, __shfl_xor_sync(0xffffffffu, v, 2));
    return v;
}
__device__ __forceinline__ float red_sum4(float v) {
    v += __shfl_xor_sync(0xffffffffu, v, 1);
    v += __shfl_xor_sync(0xffffffffu, v, 2);
    return v;
}
// swizzle for 256B rows: chunk c16 in 0..15
__device__ __forceinline__ int sw256(int r, int c16) {
    return (c16 & 8) | ((c16 ^ r) & 7);
}

__global__ __launch_bounds__(256) void attn_h_kernel()
{
    extern __shared__ char smc[];
    char* Qs = smc + AQ_OFF;
    char* Kb0 = smc + AK_OFF;
    char* Vs = smc + AV_OFF;
    char* Ps = smc + AP_OFF;

    const int qt = (int)(gridDim.x - 1) - blockIdx.x;  // big tiles first
    const int h  = blockIdx.y;
    const int b  = blockIdx.z;
    const int kvh = h / REP_;

    const int tid  = threadIdx.x;
    const int lane = tid & 31;
    const int w    = tid >> 5;
    const int lq   = lane >> 2;
    const int lr   = lane & 3;

    const float SCL = 0.08838834764831845f * 1.4426950408889634f;
    const int nkt = 2 * qt + 2;

    // prologue: Q (128x16 chunks) + K0 (64x16 chunks)
    #pragma unroll
    for (int l = 0; l < 8; l++) {
        int i = tid + l * 256;
        int r = i >> 4, c16 = i & 15;
        cp16(Qs + r * 256 + (sw256(r & 7, c16) << 4),
             &g_qproj[((long)(b * S_) + qt * 128 + r) * (H_ * HD_) + h * HD_ + c16 * 8]);
    }
    #pragma unroll
    for (int l = 0; l < 4; l++) {
        int i = tid + l * 256;
        int r = i >> 4, c16 = i & 15;
        cp16(Kb0 + r * 256 + (sw256(r & 7, c16) << 4),
             &g_kproj[((long)(b * S_) + r) * (KVH_ * HD_) + kvh * HD_ + c16 * 8]);
    }
    CP_COMMIT();

    float o[16][4];
    #pragma unroll
    for (int nt = 0; nt < 16; nt++)
        #pragma unroll
        for (int j = 0; j < 4; j++) o[nt][j] = 0.f;
    float m0 = -1e30f, m1 = -1e30f, l0 = 0.f, l1 = 0.f;

    const int qrow = w * 16 + lq;
    const unsigned v_base = (unsigned)__cvta_generic_to_shared(Vs);
    const int vt = lane >> 3;         // 0..3 (ldmatrix tile id)
    const int vl = lane & 7;          // 0..7

    for (int kt = 0; kt < nkt; kt++) {
        __syncthreads();

        // issue V(kt)
        #pragma unroll
        for (int l = 0; l < 4; l++) {
            int i = tid + l * 256;
            int r = i >> 4, c16 = i & 15;
            cp16(Vs + r * 256 + (sw256(r & 7, c16) << 4),
                 &g_vproj[((long)(b * S_) + kt * 64 + r) * (KVH_ * HD_) + kvh * HD_ + c16 * 8]);
        }
        CP_COMMIT();
        // issue K(kt+1)
        if (kt + 1 < nkt) {
            char* Kn = Kb0 + ((kt + 1) & 1) * 16384;
            #pragma unroll
            for (int l = 0; l < 4; l++) {
                int i = tid + l * 256;
                int r = i >> 4, c16 = i & 15;
                cp16(Kn + r * 256 + (sw256(r & 7, c16) << 4),
                     &g_kproj[((long)(b * S_) + (kt + 1) * 64 + r) * (KVH_ * HD_) + kvh * HD_ + c16 * 8]);
            }
            CP_COMMIT();
        }

        if (kt + 1 < nkt) { CP_WAIT(2); } else { CP_WAIT(1); }
        __syncthreads();

        const char* Kb = Kb0 + (kt & 1) * 16384;

        // ---- scores: S = Q K^T (16 x 64 per warp), 8 k16-steps ----
        float sacc[8][4];
        #pragma unroll
        for (int nt = 0; nt < 8; nt++)
            #pragma unroll
            for (int j = 0; j < 4; j++) sacc[nt][j] = 0.f;

        #pragma unroll
        for (int ks = 0; ks < 8; ks++) {
            const int c0 = sw256(lq, 2 * ks);
            const int c1 = sw256(lq, 2 * ks + 1);
            unsigned a[4];
            {
                int r0 = qrow * 256, r1 = (qrow + 8) * 256;
                a[0] = lds32(Qs + r0 + (c0 << 4) + 4 * lr);
                a[1] = lds32(Qs + r1 + (c0 << 4) + 4 * lr);
                a[2] = lds32(Qs + r0 + (c1 << 4) + 4 * lr);
                a[3] = lds32(Qs + r1 + (c1 << 4) + 4 * lr);
            }
            #pragma unroll
            for (int nt = 0; nt < 8; nt++) {
                int rn = (nt * 8 + lq) * 256;
                unsigned bb[2];
                bb[0] = lds32(Kb + rn + (c0 << 4) + 4 * lr);
                bb[1] = lds32(Kb + rn + (c1 << 4) + 4 * lr);
                mma_f16(sacc[nt], a, bb);
            }
        }

        #pragma unroll
        for (int nt = 0; nt < 8; nt++)
            #pragma unroll
            for (int j = 0; j < 4; j++) sacc[nt][j] *= SCL;

        if (kt >= 2 * qt) {
            int r0 = qt * 128 + qrow;
            int r1 = r0 + 8;
            #pragma unroll
            for (int nt = 0; nt < 8; nt++) {
                int c = kt * 64 + nt * 8 + 2 * lr;
                if (c     > r0) sacc[nt][0] = -1e30f;
                if (c + 1 > r0) sacc[nt][1] = -1e30f;
                if (c     > r1) sacc[nt][2] = -1e30f;
                if (c + 1 > r1) sacc[nt][3] = -1e30f;
            }
        }

        // ---- online softmax (base-2) ----
        float mt0 = -1e30f, mt1 = -1e30f;
        #pragma unroll
        for (int nt = 0; nt < 8; nt++) {
            mt0 = fmaxf(mt0, fmaxf(sacc[nt][0], sacc[nt][1]));
            mt1 = fmaxf(mt1, fmaxf(sacc[nt][2], sacc[nt][3]));
        }
        mt0 = red_max4(mt0);
        mt1 = red_max4(mt1);
        float mn0 = fmaxf(m0, mt0), mn1 = fmaxf(m1, mt1);
        float alpha0 = ex2f(m0 - mn0), alpha1 = ex2f(m1 - mn1);

        float rs0 = 0.f, rs1 = 0.f;
        #pragma unroll
        for (int nt = 0; nt < 8; nt++) {
            sacc[nt][0] = ex2f(sacc[nt][0] - mn0);
            sacc[nt][1] = ex2f(sacc[nt][1] - mn0);
            sacc[nt][2] = ex2f(sacc[nt][2] - mn1);
            sacc[nt][3] = ex2f(sacc[nt][3] - mn1);
            rs0 += sacc[nt][0] + sacc[nt][1];
            rs1 += sacc[nt][2] + sacc[nt][3];
        }
        rs0 = red_sum4(rs0);
        rs1 = red_sum4(rs1);
        l0 = l0 * alpha0 + rs0;
        l1 = l1 * alpha1 + rs1;
        m0 = mn0; m1 = mn1;

        #pragma unroll
        for (int nt = 0; nt < 16; nt++) {
            o[nt][0] *= alpha0; o[nt][1] *= alpha0;
            o[nt][2] *= alpha1; o[nt][3] *= alpha1;
        }

        // ---- store P (half2) to swizzled Ps [128 rows][128B] ----
        #pragma unroll
        for (int nt = 0; nt < 8; nt++) {
            int sw = ((nt ^ lq) & 7) << 4;
            *reinterpret_cast<unsigned*>(Ps + qrow * 128 + sw + 4 * lr) =
                pack_h2(sacc[nt][0], sacc[nt][1]);
            *reinterpret_cast<unsigned*>(Ps + (qrow + 8) * 128 + sw + 4 * lr) =
                pack_h2(sacc[nt][2], sacc[nt][3]);
        }
        __syncwarp();

        // wait for V(kt)
        if (kt + 1 < nkt) { CP_WAIT(1); } else { CP_WAIT(0); }
        __syncthreads();

        // ---- O += P V : 4 k16-steps, B frags via ldmatrix.x4.trans ----
        #pragma unroll
        for (int ks = 0; ks < 4; ks++) {
            const int k0 = ks * 16;
            const int pc0 = ((2 * ks) ^ lq) & 7;
            const int pc1 = ((2 * ks + 1) ^ lq) & 7;
            unsigned a[4];
            {
                int r0 = qrow * 128, r1 = (qrow + 8) * 128;
                a[0] = lds32(Ps + r0 + (pc0 << 4) + 4 * lr);
                a[1] = lds32(Ps + r1 + (pc0 << 4) + 4 * lr);
                a[2] = lds32(Ps + r0 + (pc1 << 4) + 4 * lr);
                a[3] = lds32(Ps + r1 + (pc1 << 4) + 4 * lr);
            }
            const int vrow = k0 + ((vt & 1) << 3) + vl;
            #pragma unroll
            for (int ntt = 0; ntt < 8; ntt++) {
                int c16 = 2 * ntt + (vt >> 1);
                unsigned addr = v_base + vrow * 256 + (sw256(vl, c16) << 4);
                unsigned v0, v1, v2, v3;
                ldmatrix_x4_trans(v0, v1, v2, v3, addr);
                unsigned b0[2] = {v0, v1};
                unsigned b1[2] = {v2, v3};
                mma_f16(o[2 * ntt],     a, b0);
                mma_f16(o[2 * ntt + 1], a, b1);
            }
        }
    }

    // ---- epilogue: normalize, store half ----
    float inv0 = 1.0f / l0;
    float inv1 = 1.0f / l1;
    long base0 = ((long)(b * S_) + qt * 128 + qrow) * (H_ * HD_) + h * HD_;
    long base1 = base0 + (long)8 * (H_ * HD_);
    #pragma unroll
    for (int nt = 0; nt < 16; nt++) {
        int c = nt * 8 + 2 * lr;
        *reinterpret_cast<unsigned*>(&g_attn[base0 + c]) =
            pack_h2(o[nt][0] * inv0, o[nt][1] * inv0);
        *reinterpret_cast<unsigned*>(&g_attn[base1 + c]) =
            pack_h2(o[nt][2] * inv1, o[nt][3] * inv1);
    }
}

// ---------------------------------------------------------------------------
extern "C" void kernel_launch(void* const* d_in, const int* in_sizes, int n_in,
                              void* d_out, int out_size)
{
    const float* x  = (const float*)d_in[0];
    const float* Wq = (const float*)d_in[1];
    const float* Wk = (const float*)d_in[2];
    const float* Wv = (const float*)d_in[3];
    const float* Wo = (const float*)d_in[4];
    float* out = (float*)d_out;

    __half *xh, *wqh, *wkh, *wvh, *woh, *qproj, *kproj, *vproj, *attn;
    cudaGetSymbolAddress((void**)&xh,  g_xh);
    cudaGetSymbolAddress((void**)&wqh, g_wqh);
    cudaGetSymbolAddress((void**)&wkh, g_wkh);
    cudaGetSymbolAddress((void**)&wvh, g_wvh);
    cudaGetSymbolAddress((void**)&woh, g_woh);
    cudaGetSymbolAddress((void**)&qproj, g_qproj);
    cudaGetSymbolAddress((void**)&kproj, g_kproj);
    cudaGetSymbolAddress((void**)&vproj, g_vproj);
    cudaGetSymbolAddress((void**)&attn,  g_attn);

    const int M = B_ * S_;   // 4096

    // operand prep
    convert_half_kernel<<<(B_*S_*D_/4 + 255)/256, 256>>>(x, xh, B_*S_*D_/4);
    transpose_convert_kernel<<<dim3((H_*HD_)/32,   D_/32), dim3(32,8)>>>(Wq, wqh, D_, H_*HD_);
    transpose_convert_kernel<<<dim3((KVH_*HD_)/32, D_/32), dim3(32,8)>>>(Wk, wkh, D_, KVH_*HD_);
    transpose_convert_kernel<<<dim3((KVH_*HD_)/32, D_/32), dim3(32,8)>>>(Wv, wvh, D_, KVH_*HD_);
    transpose_convert_kernel<<<dim3(D_/32, (H_*HD_)/32), dim3(32,8)>>>(Wo, woh, H_*HD_, D_);

    cudaFuncSetAttribute(h_gemm_kernel<true>,
                         cudaFuncAttributeMaxDynamicSharedMemorySize, HSM_TOTAL);
    cudaFuncSetAttribute(h_gemm_kernel<false>,
                         cudaFuncAttributeMaxDynamicSharedMemorySize, HSM_TOTAL);

    // QKV projections (fp16 in/out, fp32 accum)
    h_gemm_kernel<true><<<dim3((H_*HD_)/128,   M/128), 256, HSM_TOTAL>>>(
        xh, wqh, qproj, M, H_*HD_,   D_);
    h_gemm_kernel<true><<<dim3((KVH_*HD_)/128, M/128), 256, HSM_TOTAL>>>(
        xh, wkh, kproj, M, KVH_*HD_, D_);
    h_gemm_kernel<true><<<dim3((KVH_*HD_)/128, M/128), 256, HSM_TOTAL>>>(
        xh, wvh, vproj, M, KVH_*HD_, D_);

    // RoPE in-place
    rope_half_kernel<<<(B_*S_*H_*64)/256,   256>>>(qproj, H_);
    rope_half_kernel<<<(B_*S_*KVH_*64)/256, 256>>>(kproj, KVH_);

    // Flash attention (fp16 mma)
    cudaFuncSetAttribute(attn_h_kernel,
                         cudaFuncAttributeMaxDynamicSharedMemorySize, ATTN_SMEM_BYTES);
    attn_h_kernel<<<dim3(S_/128, H_, B_), 256, ATTN_SMEM_BYTES>>>();

    // Output projection (fp32 out)
    h_gemm_kernel<false><<<dim3(D_/128, M/128), 256, HSM_TOTAL>>>(
        attn, woh, out, M, D_, D_);
}

// round 10
// speedup vs baseline: 8.0182x; 1.1401x over previous
#include <cuda_runtime.h>
#include <cuda_fp16.h>
#include <math.h>
#include <stdint.h>

#define B_ 2
#define S_ 2048
#define D_ 2048
#define H_ 16
#define KVH_ 4
#define HD_ 128
#define REP_ (H_/KVH_)
#define QKV_N 3072          // 2048 Q | 512 K | 512 V

// Scratch (device globals: allocation-free)
__device__ __half g_xh   [B_*S_*D_];
__device__ __half g_wqkv [QKV_N*D_];       // [N,K] fused Q|K|V weights
__device__ __half g_woh  [D_*H_*HD_];      // [N,K]
__device__ __half g_qkv  [B_*S_*QKV_N];    // fused projections
__device__ __half g_attn [B_*S_*H_*HD_];
__device__ float2 g_ropetab[S_*64];

// ---------------------------------------------------------------------------
// helpers
// ---------------------------------------------------------------------------
__device__ __forceinline__ float ex2f(float x) {
    float r;
    asm("ex2.approx.ftz.f32 %0, %1;" : "=f"(r) : "f"(x));
    return r;
}
__device__ __forceinline__ void mma_f16(
    float* c, const unsigned* a, const unsigned* b)
{
    asm volatile(
        "mma.sync.aligned.m16n8k16.row.col.f32.f16.f16.f32 "
        "{%0,%1,%2,%3}, {%4,%5,%6,%7}, {%8,%9}, {%0,%1,%2,%3};"
        : "+f"(c[0]), "+f"(c[1]), "+f"(c[2]), "+f"(c[3])
        : "r"(a[0]), "r"(a[1]), "r"(a[2]), "r"(a[3]),
          "r"(b[0]), "r"(b[1]));
}
__device__ __forceinline__ void cp16(void* s, const void* g) {
    unsigned sa = (unsigned)__cvta_generic_to_shared(s);
    asm volatile("cp.async.cg.shared.global [%0], [%1], 16;" :: "r"(sa), "l"(g));
}
#define CP_COMMIT()  asm volatile("cp.async.commit_group;")
#define CP_WAIT(n)   asm volatile("cp.async.wait_group %0;" :: "n"(n))

__device__ __forceinline__ void ldmx4(
    unsigned& r0, unsigned& r1, unsigned& r2, unsigned& r3, unsigned addr)
{
    asm volatile(
        "ldmatrix.sync.aligned.m8n8.x4.shared.b16 {%0,%1,%2,%3}, [%4];"
        : "=r"(r0), "=r"(r1), "=r"(r2), "=r"(r3) : "r"(addr));
}
__device__ __forceinline__ void ldmx4_trans(
    unsigned& r0, unsigned& r1, unsigned& r2, unsigned& r3, unsigned addr)
{
    asm volatile(
        "ldmatrix.sync.aligned.m8n8.x4.trans.shared.b16 {%0,%1,%2,%3}, [%4];"
        : "=r"(r0), "=r"(r1), "=r"(r2), "=r"(r3) : "r"(addr));
}
__device__ __forceinline__ unsigned pack_h2(float lo, float hi) {
    __half2 h = __floats2half2_rn(lo, hi);
    return *reinterpret_cast<unsigned*>(&h);
}

// ---------------------------------------------------------------------------
// prep kernels
// ---------------------------------------------------------------------------
__global__ void convert_half_kernel(const float* __restrict__ in,
                                    __half* __restrict__ out, int n4)
{
    int i = blockIdx.x * blockDim.x + threadIdx.x;
    if (i < n4) {
        float4 v = reinterpret_cast<const float4*>(in)[i];
        uint2 u;
        u.x = pack_h2(v.x, v.y);
        u.y = pack_h2(v.z, v.w);
        reinterpret_cast<uint2*>(out)[i] = u;
    }
}

__global__ void transpose_convert_kernel(const float* __restrict__ in,
                                         __half* __restrict__ out, int K, int N)
{
    __shared__ float t[32][33];
    int k0 = blockIdx.y * 32, n0 = blockIdx.x * 32;
    int x = threadIdx.x, y = threadIdx.y;
    #pragma unroll
    for (int i = 0; i < 32; i += 8)
        t[y + i][x] = in[(long)(k0 + y + i) * N + n0 + x];
    __syncthreads();
    #pragma unroll
    for (int i = 0; i < 32; i += 8)
        out[(long)(n0 + y + i) * K + k0 + x] = __float2half_rn(t[x][y + i]);
}

__global__ void ropetab_kernel()
{
    int id = blockIdx.x * blockDim.x + threadIdx.x;   // 0 .. S*64-1
    int s = id >> 6, i = id & 63;
    float inv = exp2f(-(float)i * (13.287712379549449f / 64.0f));
    float sn, cs;
    sincosf((float)s * inv, &sn, &cs);
    g_ropetab[id] = make_float2(cs, sn);
}

// RoPE over fused qkv buffer: 20 rotated heads (16 Q + 4 K)
__global__ void rope_qkv_kernel()
{
    long idx = (long)blockIdx.x * blockDim.x + threadIdx.x;
    int i = (int)(idx & 63);
    long t = idx >> 6;
    int h20 = (int)(t % 20);
    long row = t / 20;
    int s = (int)(row % S_);

    float2 cssn = g_ropetab[s * 64 + i];
    int col = (h20 < 16) ? h20 * 128 : 2048 + (h20 - 16) * 128;
    __half* p = g_qkv + row * QKV_N + col;
    float x1 = __half2float(p[i]);
    float x2 = __half2float(p[i + 64]);
    p[i]      = __float2half_rn(x1 * cssn.x - x2 * cssn.y);
    p[i + 64] = __float2half_rn(x2 * cssn.x + x1 * cssn.y);
}

// ---------------------------------------------------------------------------
// FP16 GEMM: C[M,N] = A[M,K] @ Bt[N,K]^T, fp32 accum, ldmatrix fragments.
// 256 threads (8 warps 2x4), CTA tile 128x128, BK=64, 3-stage cp.async ring.
// ---------------------------------------------------------------------------
#define HT_BYTES (128*128)
#define HNS 3
#define HSM_TOTAL (2*HNS*HT_BYTES)   // 98304

template<bool HOUT>
__global__ __launch_bounds__(256) void h_gemm_kernel(
    const __half* __restrict__ A, const __half* __restrict__ Bt,
    void* __restrict__ Cv, int M, int N, int K)
{
    extern __shared__ char smem[];
    char* AsBase = smem;
    char* BsBase = smem + HNS * HT_BYTES;
    const unsigned smem32 = (unsigned)__cvta_generic_to_shared(smem);

    const int tid  = threadIdx.x;
    const int lane = tid & 31;
    const int warp = tid >> 5;
    const int wm   = warp >> 2;
    const int wn   = warp & 3;
    const int bm   = blockIdx.y * 128;
    const int bn   = blockIdx.x * 128;
    const int lq = lane >> 2;
    const int lr = lane & 3;

    // ldmatrix lane-address precompute
    const int a_rl = (lane & 7) + ((lane & 8) ? 8 : 0);   // A/P row-local
    const int a_ch = lane >> 4;                            // A chunk offset
    const int b_rl = (lane & 7) + ((lane & 16) ? 8 : 0);   // B row-local
    const int b_ch = (lane >> 3) & 1;                      // B chunk offset

    float acc[4][4][4];
    #pragma unroll
    for (int mt = 0; mt < 4; mt++)
        #pragma unroll
        for (int nt = 0; nt < 4; nt++)
            #pragma unroll
            for (int i = 0; i < 4; i++) acc[mt][nt][i] = 0.f;

    const int NK = K >> 6;

    auto fill = [&](int j, int s) {
        char* As = AsBase + s * HT_BYTES;
        char* Bs = BsBase + s * HT_BYTES;
        const __half* Ag = A  + (long)bm * K + j * 64;
        const __half* Bg = Bt + (long)bn * K + j * 64;
        #pragma unroll
        for (int l = 0; l < 4; l++) {
            int idx = tid + l * 256;
            int r = idx >> 3, c8 = idx & 7;
            int dst = r * 128 + ((c8 ^ (r & 7)) << 4);
            cp16(As + dst, Ag + (long)r * K + c8 * 8);
            cp16(Bs + dst, Bg + (long)r * K + c8 * 8);
        }
        CP_COMMIT();
    };

    fill(0, 0);
    if (NK > 1) fill(1, 1);

    // per-lane row bases (byte offsets within a tile)
    int arow[4], brow[2];
    #pragma unroll
    for (int mt = 0; mt < 4; mt++) arow[mt] = wm * 64 + mt * 16 + a_rl;
    #pragma unroll
    for (int p = 0; p < 2; p++) brow[p] = wn * 32 + p * 16 + b_rl;

    for (int it = 0; it < NK; it++) {
        if (it + 1 < NK) { CP_WAIT(1); } else { CP_WAIT(0); }
        __syncthreads();
        if (it + 2 < NK) fill(it + 2, (it + 2) % 3);

        const unsigned Ab = smem32 + (it % 3) * HT_BYTES;
        const unsigned Bb = smem32 + (HNS + it % 3) * HT_BYTES;

        #pragma unroll
        for (int ks = 0; ks < 4; ks++) {
            unsigned a[4][4], b[4][2];
            #pragma unroll
            for (int mt = 0; mt < 4; mt++) {
                int ch = 2 * ks + a_ch;
                unsigned addr = Ab + arow[mt] * 128 + ((ch ^ (arow[mt] & 7)) << 4);
                ldmx4(a[mt][0], a[mt][1], a[mt][2], a[mt][3], addr);
            }
            #pragma unroll
            for (int p = 0; p < 2; p++) {
                int ch = 2 * ks + b_ch;
                unsigned addr = Bb + brow[p] * 128 + ((ch ^ (brow[p] & 7)) << 4);
                ldmx4(b[2*p][0], b[2*p][1], b[2*p+1][0], b[2*p+1][1], addr);
            }
            #pragma unroll
            for (int mt = 0; mt < 4; mt++)
                #pragma unroll
                for (int nt = 0; nt < 4; nt++)
                    mma_f16(acc[mt][nt], a[mt], b[nt]);
        }
        __syncthreads();
    }

    #pragma unroll
    for (int mt = 0; mt < 4; mt++) {
        long row0 = bm + wm * 64 + mt * 16 + lq;
        long row1 = row0 + 8;
        #pragma unroll
        for (int nt = 0; nt < 4; nt++) {
            int col = bn + wn * 32 + nt * 8 + 2 * lr;
            if (HOUT) {
                __half* C = (__half*)Cv;
                *reinterpret_cast<unsigned*>(&C[row0 * N + col]) =
                    pack_h2(acc[mt][nt][0], acc[mt][nt][1]);
                *reinterpret_cast<unsigned*>(&C[row1 * N + col]) =
                    pack_h2(acc[mt][nt][2], acc[mt][nt][3]);
            } else {
                float* C = (float*)Cv;
                *reinterpret_cast<float2*>(&C[row0 * N + col]) =
                    make_float2(acc[mt][nt][0], acc[mt][nt][1]);
                *reinterpret_cast<float2*>(&C[row1 * N + col]) =
                    make_float2(acc[mt][nt][2], acc[mt][nt][3]);
            }
        }
    }
}

// ---------------------------------------------------------------------------
// FP16 flash attention, ldmatrix fragments, cp.async pipelined, causal.
// Grid (S/128, H, B), 256 threads (8 warps), warp = 16 q rows.
// ---------------------------------------------------------------------------
#define AQ_OFF 0
#define AK_OFF 32768
#define AV_OFF 65536
#define AP_OFF 81920
#define ATTN_SMEM_BYTES 98304

__device__ __forceinline__ float red_max4(float v) {
    v = fmaxf(v, __shfl_xor_sync(0xffffffffu, v, 1));
    v = fmaxf(v, __shfl_xor_sync(0xffffffffu, v, 2));
    return v;
}
__device__ __forceinline__ float red_sum4(float v) {
    v += __shfl_xor_sync(0xffffffffu, v, 1);
    v += __shfl_xor_sync(0xffffffffu, v, 2);
    return v;
}
__device__ __forceinline__ int sw256(int r, int c16) {
    return (c16 & 8) | ((c16 ^ r) & 7);
}

__global__ __launch_bounds__(256) void attn_h_kernel()
{
    extern __shared__ char smc[];
    char* Qs = smc + AQ_OFF;
    char* Kb0 = smc + AK_OFF;
    char* Vs = smc + AV_OFF;
    char* Ps = smc + AP_OFF;
    const unsigned smem32 = (unsigned)__cvta_generic_to_shared(smc);

    const int qt = (int)(gridDim.x - 1) - blockIdx.x;
    const int h  = blockIdx.y;
    const int b  = blockIdx.z;
    const int kvh = h / REP_;

    const int tid  = threadIdx.x;
    const int lane = tid & 31;
    const int w    = tid >> 5;
    const int lq   = lane >> 2;
    const int lr   = lane & 3;

    const int a_rl = (lane & 7) + ((lane & 8) ? 8 : 0);
    const int a_ch = lane >> 4;
    const int b_rl = (lane & 7) + ((lane & 16) ? 8 : 0);
    const int b_ch = (lane >> 3) & 1;

    const float SCL = 0.08838834764831845f * 1.4426950408889634f;
    const int nkt = 2 * qt + 2;

    const long rowbase = (long)(b * S_);
    const int qcol = h * 128;
    const int kcol = 2048 + kvh * 128;
    const int vcol = 2560 + kvh * 128;

    // prologue: Q + K0
    #pragma unroll
    for (int l = 0; l < 8; l++) {
        int i = tid + l * 256;
        int r = i >> 4, c16 = i & 15;
        cp16(Qs + r * 256 + (sw256(r & 7, c16) << 4),
             &g_qkv[(rowbase + qt * 128 + r) * QKV_N + qcol + c16 * 8]);
    }
    #pragma unroll
    for (int l = 0; l < 4; l++) {
        int i = tid + l * 256;
        int r = i >> 4, c16 = i & 15;
        cp16(Kb0 + r * 256 + (sw256(r & 7, c16) << 4),
             &g_qkv[(rowbase + r) * QKV_N + kcol + c16 * 8]);
    }
    CP_COMMIT();

    float o[16][4];
    #pragma unroll
    for (int nt = 0; nt < 16; nt++)
        #pragma unroll
        for (int j = 0; j < 4; j++) o[nt][j] = 0.f;
    float m0 = -1e30f, m1 = -1e30f, l0 = 0.f, l1 = 0.f;

    const int qrow = w * 16 + lq;
    const int aqrow = w * 16 + a_rl;          // ldmatrix A row (Q and P)
    const unsigned v_base = smem32 + AV_OFF;
    const int vt = lane >> 3;
    const int vl = lane & 7;

    for (int kt = 0; kt < nkt; kt++) {
        __syncthreads();

        #pragma unroll
        for (int l = 0; l < 4; l++) {
            int i = tid + l * 256;
            int r = i >> 4, c16 = i & 15;
            cp16(Vs + r * 256 + (sw256(r & 7, c16) << 4),
                 &g_qkv[(rowbase + kt * 64 + r) * QKV_N + vcol + c16 * 8]);
        }
        CP_COMMIT();
        if (kt + 1 < nkt) {
            char* Kn = Kb0 + ((kt + 1) & 1) * 16384;
            #pragma unroll
            for (int l = 0; l < 4; l++) {
                int i = tid + l * 256;
                int r = i >> 4, c16 = i & 15;
                cp16(Kn + r * 256 + (sw256(r & 7, c16) << 4),
                     &g_qkv[(rowbase + (kt + 1) * 64 + r) * QKV_N + kcol + c16 * 8]);
            }
            CP_COMMIT();
        }

        if (kt + 1 < nkt) { CP_WAIT(2); } else { CP_WAIT(1); }
        __syncthreads();

        const unsigned Kb = smem32 + AK_OFF + (kt & 1) * 16384;
        const unsigned Qb = smem32 + AQ_OFF;

        // ---- scores: S = Q K^T, ldmatrix frags ----
        float sacc[8][4];
        #pragma unroll
        for (int nt = 0; nt < 8; nt++)
            #pragma unroll
            for (int j = 0; j < 4; j++) sacc[nt][j] = 0.f;

        #pragma unroll
        for (int ks = 0; ks < 8; ks++) {
            unsigned a[4];
            {
                int ch = 2 * ks + a_ch;
                unsigned addr = Qb + aqrow * 256 + (sw256(aqrow & 7, ch) << 4);
                ldmx4(a[0], a[1], a[2], a[3], addr);
            }
            #pragma unroll
            for (int p = 0; p < 4; p++) {
                int row = p * 16 + b_rl;
                int ch = 2 * ks + b_ch;
                unsigned addr = Kb + row * 256 + (sw256(row & 7, ch) << 4);
                unsigned b0[2], b1[2];
                ldmx4(b0[0], b0[1], b1[0], b1[1], addr);
                mma_f16(sacc[2*p],     a, b0);
                mma_f16(sacc[2*p + 1], a, b1);
            }
        }

        #pragma unroll
        for (int nt = 0; nt < 8; nt++)
            #pragma unroll
            for (int j = 0; j < 4; j++) sacc[nt][j] *= SCL;

        if (kt >= 2 * qt) {
            int r0 = qt * 128 + qrow;
            int r1 = r0 + 8;
            #pragma unroll
            for (int nt = 0; nt < 8; nt++) {
                int c = kt * 64 + nt * 8 + 2 * lr;
                if (c     > r0) sacc[nt][0] = -1e30f;
                if (c + 1 > r0) sacc[nt][1] = -1e30f;
                if (c     > r1) sacc[nt][2] = -1e30f;
                if (c + 1 > r1) sacc[nt][3] = -1e30f;
            }
        }

        // ---- online softmax (base-2) ----
        float mt0 = -1e30f, mt1 = -1e30f;
        #pragma unroll
        for (int nt = 0; nt < 8; nt++) {
            mt0 = fmaxf(mt0, fmaxf(sacc[nt][0], sacc[nt][1]));
            mt1 = fmaxf(mt1, fmaxf(sacc[nt][2], sacc[nt][3]));
        }
        mt0 = red_max4(mt0);
        mt1 = red_max4(mt1);
        float mn0 = fmaxf(m0, mt0), mn1 = fmaxf(m1, mt1);
        float alpha0 = ex2f(m0 - mn0), alpha1 = ex2f(m1 - mn1);

        float rs0 = 0.f, rs1 = 0.f;
        #pragma unroll
        for (int nt = 0; nt < 8; nt++) {
            sacc[nt][0] = ex2f(sacc[nt][0] - mn0);
            sacc[nt][1] = ex2f(sacc[nt][1] - mn0);
            sacc[nt][2] = ex2f(sacc[nt][2] - mn1);
            sacc[nt][3] = ex2f(sacc[nt][3] - mn1);
            rs0 += sacc[nt][0] + sacc[nt][1];
            rs1 += sacc[nt][2] + sacc[nt][3];
        }
        rs0 = red_sum4(rs0);
        rs1 = red_sum4(rs1);
        l0 = l0 * alpha0 + rs0;
        l1 = l1 * alpha1 + rs1;
        m0 = mn0; m1 = mn1;

        #pragma unroll
        for (int nt = 0; nt < 16; nt++) {
            o[nt][0] *= alpha0; o[nt][1] *= alpha0;
            o[nt][2] *= alpha1; o[nt][3] *= alpha1;
        }

        // ---- store P (half2) to swizzled Ps [128 rows][128B] ----
        #pragma unroll
        for (int nt = 0; nt < 8; nt++) {
            int sw = ((nt ^ lq) & 7) << 4;
            *reinterpret_cast<unsigned*>(Ps + qrow * 128 + sw + 4 * lr) =
                pack_h2(sacc[nt][0], sacc[nt][1]);
            *reinterpret_cast<unsigned*>(Ps + (qrow + 8) * 128 + sw + 4 * lr) =
                pack_h2(sacc[nt][2], sacc[nt][3]);
        }
        __syncwarp();

        if (kt + 1 < nkt) { CP_WAIT(1); } else { CP_WAIT(0); }
        __syncthreads();

        // ---- O += P V ----
        const unsigned Pb = smem32 + AP_OFF;
        #pragma unroll
        for (int ks = 0; ks < 4; ks++) {
            unsigned a[4];
            {
                int ch = 2 * ks + a_ch;     // ch <= 7
                unsigned addr = Pb + aqrow * 128 + (((ch ^ (aqrow & 7)) & 7) << 4);
                ldmx4(a[0], a[1], a[2], a[3], addr);
            }
            const int vrow = ks * 16 + ((vt & 1) << 3) + vl;
            #pragma unroll
            for (int ntt = 0; ntt < 8; ntt++) {
                int c16 = 2 * ntt + (vt >> 1);
                unsigned addr = v_base + vrow * 256 + (sw256(vl, c16) << 4);
                unsigned v0, v1, v2, v3;
                ldmx4_trans(v0, v1, v2, v3, addr);
                unsigned b0[2] = {v0, v1};
                unsigned b1[2] = {v2, v3};
                mma_f16(o[2 * ntt],     a, b0);
                mma_f16(o[2 * ntt + 1], a, b1);
            }
        }
    }

    // ---- epilogue ----
    float inv0 = 1.0f / l0;
    float inv1 = 1.0f / l1;
    long base0 = (rowbase + qt * 128 + qrow) * (H_ * HD_) + h * HD_;
    long base1 = base0 + (long)8 * (H_ * HD_);
    #pragma unroll
    for (int nt = 0; nt < 16; nt++) {
        int c = nt * 8 + 2 * lr;
        *reinterpret_cast<unsigned*>(&g_attn[base0 + c]) =
            pack_h2(o[nt][0] * inv0, o[nt][1] * inv0);
        *reinterpret_cast<unsigned*>(&g_attn[base1 + c]) =
            pack_h2(o[nt][2] * inv1, o[nt][3] * inv1);
    }
}

// ---------------------------------------------------------------------------
extern "C" void kernel_launch(void* const* d_in, const int* in_sizes, int n_in,
                              void* d_out, int out_size)
{
    const float* x  = (const float*)d_in[0];
    const float* Wq = (const float*)d_in[1];
    const float* Wk = (const float*)d_in[2];
    const float* Wv = (const float*)d_in[3];
    const float* Wo = (const float*)d_in[4];
    float* out = (float*)d_out;

    __half *xh, *wqkv, *woh, *qkv, *attn;
    cudaGetSymbolAddress((void**)&xh,   g_xh);
    cudaGetSymbolAddress((void**)&wqkv, g_wqkv);
    cudaGetSymbolAddress((void**)&woh,  g_woh);
    cudaGetSymbolAddress((void**)&qkv,  g_qkv);
    cudaGetSymbolAddress((void**)&attn, g_attn);

    const int M = B_ * S_;   // 4096

    // operand prep
    convert_half_kernel<<<(B_*S_*D_/4 + 255)/256, 256>>>(x, xh, B_*S_*D_/4);
    transpose_convert_kernel<<<dim3((H_*HD_)/32,   D_/32), dim3(32,8)>>>(
        Wq, wqkv, D_, H_*HD_);
    transpose_convert_kernel<<<dim3((KVH_*HD_)/32, D_/32), dim3(32,8)>>>(
        Wk, wqkv + 2048 * D_, D_, KVH_*HD_);
    transpose_convert_kernel<<<dim3((KVH_*HD_)/32, D_/32), dim3(32,8)>>>(
        Wv, wqkv + 2560 * D_, D_, KVH_*HD_);
    transpose_convert_kernel<<<dim3(D_/32, (H_*HD_)/32), dim3(32,8)>>>(
        Wo, woh, H_*HD_, D_);
    ropetab_kernel<<<(S_*64)/256, 256>>>();

    cudaFuncSetAttribute(h_gemm_kernel<true>,
                         cudaFuncAttributeMaxDynamicSharedMemorySize, HSM_TOTAL);
    cudaFuncSetAttribute(h_gemm_kernel<false>,
                         cudaFuncAttributeMaxDynamicSharedMemorySize, HSM_TOTAL);

    // fused QKV projection
    h_gemm_kernel<true><<<dim3(QKV_N/128, M/128), 256, HSM_TOTAL>>>(
        xh, wqkv, qkv, M, QKV_N, D_);

    // RoPE (q + k heads) via table
    rope_qkv_kernel<<<(M * 20 * 64)/256, 256>>>();

    // Flash attention
    cudaFuncSetAttribute(attn_h_kernel,
                         cudaFuncAttributeMaxDynamicSharedMemorySize, ATTN_SMEM_BYTES);
    attn_h_kernel<<<dim3(S_/128, H_, B_), 256, ATTN_SMEM_BYTES>>>();

    // Output projection (fp32 out)
    h_gemm_kernel<false><<<dim3(D_/128, M/128), 256, HSM_TOTAL>>>(
        attn, woh, out, M, D_, D_);
}

// round 13
// speedup vs baseline: 8.4250x; 1.0507x over previous
#include <cuda_runtime.h>
#include <cuda_fp16.h>
#include <math.h>
#include <stdint.h>

#define B_ 2
#define S_ 2048
#define D_ 2048
#define H_ 16
#define KVH_ 4
#define HD_ 128
#define REP_ (H_/KVH_)
#define QKV_N 3072          // 2048 Q | 512 K | 512 V

// Scratch (device globals: allocation-free)
__device__ __half g_xh   [B_*S_*D_];
__device__ __half g_wqkv [QKV_N*D_];       // [N,K] fused Q|K|V weights
__device__ __half g_woh  [D_*H_*HD_];      // [N,K]
__device__ __half g_qkv  [B_*S_*QKV_N];    // fused projections
__device__ __half g_attn [B_*S_*H_*HD_];
__device__ float2 g_ropetab[S_*64];

// ---------------------------------------------------------------------------
// helpers
// ---------------------------------------------------------------------------
__device__ __forceinline__ float ex2f(float x) {
    float r;
    asm("ex2.approx.ftz.f32 %0, %1;" : "=f"(r) : "f"(x));
    return r;
}
__device__ __forceinline__ void mma_f16(
    float* c, const unsigned* a, const unsigned* b)
{
    asm volatile(
        "mma.sync.aligned.m16n8k16.row.col.f32.f16.f16.f32 "
        "{%0,%1,%2,%3}, {%4,%5,%6,%7}, {%8,%9}, {%0,%1,%2,%3};"
        : "+f"(c[0]), "+f"(c[1]), "+f"(c[2]), "+f"(c[3])
        : "r"(a[0]), "r"(a[1]), "r"(a[2]), "r"(a[3]),
          "r"(b[0]), "r"(b[1]));
}
__device__ __forceinline__ void cp16(void* s, const void* g) {
    unsigned sa = (unsigned)__cvta_generic_to_shared(s);
    asm volatile("cp.async.cg.shared.global [%0], [%1], 16;" :: "r"(sa), "l"(g));
}
#define CP_COMMIT()  asm volatile("cp.async.commit_group;")
#define CP_WAIT(n)   asm volatile("cp.async.wait_group %0;" :: "n"(n))

__device__ __forceinline__ void ldmx4(
    unsigned& r0, unsigned& r1, unsigned& r2, unsigned& r3, unsigned addr)
{
    asm volatile(
        "ldmatrix.sync.aligned.m8n8.x4.shared.b16 {%0,%1,%2,%3}, [%4];"
        : "=r"(r0), "=r"(r1), "=r"(r2), "=r"(r3) : "r"(addr));
}
__device__ __forceinline__ void ldmx4_trans(
    unsigned& r0, unsigned& r1, unsigned& r2, unsigned& r3, unsigned addr)
{
    asm volatile(
        "ldmatrix.sync.aligned.m8n8.x4.trans.shared.b16 {%0,%1,%2,%3}, [%4];"
        : "=r"(r0), "=r"(r1), "=r"(r2), "=r"(r3) : "r"(addr));
}
__device__ __forceinline__ unsigned pack_h2(float lo, float hi) {
    __half2 h = __floats2half2_rn(lo, hi);
    return *reinterpret_cast<unsigned*>(&h);
}

// ---------------------------------------------------------------------------
// prep: x convert (blocks 0..8191) + rope table (blocks 8192..8703)
// ---------------------------------------------------------------------------
#define XCONV_BLOCKS 8192
__global__ void prep_x_kernel(const float* __restrict__ x)
{
    int bid = blockIdx.x;
    if (bid < XCONV_BLOCKS) {
        int i = bid * blockDim.x + threadIdx.x;   // < 2097152 = B*S*D/4
        float4 v = reinterpret_cast<const float4*>(x)[i];
        uint2 u;
        u.x = pack_h2(v.x, v.y);
        u.y = pack_h2(v.z, v.w);
        reinterpret_cast<uint2*>(g_xh)[i] = u;
    } else {
        int id = (bid - XCONV_BLOCKS) * blockDim.x + threadIdx.x;  // < S*64
        int s = id >> 6, i = id & 63;
        float inv = exp2f(-(float)i * (13.287712379549449f / 64.0f));
        float sn, cs;
        sincosf((float)s * inv, &sn, &cs);
        g_ropetab[id] = make_float2(cs, sn);
    }
}

// ---------------------------------------------------------------------------
// prep: all 4 weight transposes in one launch.
// y: 0..63 Wq -> wqkv[0..2048), 64..79 Wk -> wqkv+2048*D, 80..95 Wv -> +2560*D,
//    96..159 Wo -> woh. All outputs are [N,K] with K=2048.
// ---------------------------------------------------------------------------
__global__ void prep_w_kernel(const float* __restrict__ Wq,
                              const float* __restrict__ Wk,
                              const float* __restrict__ Wv,
                              const float* __restrict__ Wo)
{
    __shared__ float t[32][33];
    const int yb = blockIdx.y;
    const float* in; __half* out; int N; int n0;
    if (yb < 64)       { in = Wq; out = g_wqkv;             N = 2048; n0 = yb * 32; }
    else if (yb < 80)  { in = Wk; out = g_wqkv + 2048 * D_; N = 512;  n0 = (yb - 64) * 32; }
    else if (yb < 96)  { in = Wv; out = g_wqkv + 2560 * D_; N = 512;  n0 = (yb - 80) * 32; }
    else               { in = Wo; out = g_woh;              N = 2048; n0 = (yb - 96) * 32; }
    const int k0 = blockIdx.x * 32;
    const int x = threadIdx.x, y = threadIdx.y;
    #pragma unroll
    for (int i = 0; i < 32; i += 8)
        t[y + i][x] = in[(long)(k0 + y + i) * N + n0 + x];
    __syncthreads();
    #pragma unroll
    for (int i = 0; i < 32; i += 8)
        out[(long)(n0 + y + i) * 2048 + k0 + x] = __float2half_rn(t[x][y + i]);
}

// RoPE over fused qkv buffer: 20 rotated heads (16 Q + 4 K)
__global__ void rope_qkv_kernel()
{
    long idx = (long)blockIdx.x * blockDim.x + threadIdx.x;
    int i = (int)(idx & 63);
    long t = idx >> 6;
    int h20 = (int)(t % 20);
    long row = t / 20;
    int s = (int)(row % S_);

    float2 cssn = g_ropetab[s * 64 + i];
    int col = (h20 < 16) ? h20 * 128 : 2048 + (h20 - 16) * 128;
    __half* p = g_qkv + row * QKV_N + col;
    float x1 = __half2float(p[i]);
    float x2 = __half2float(p[i + 64]);
    p[i]      = __float2half_rn(x1 * cssn.x - x2 * cssn.y);
    p[i + 64] = __float2half_rn(x2 * cssn.x + x1 * cssn.y);
}

// ---------------------------------------------------------------------------
// FP16 GEMM: C[M,N] = A[M,K] @ Bt[N,K]^T, fp32 accum, ldmatrix fragments.
// 256 threads (8 warps 2x4), CTA tile 128x128, BK=64, 3-stage cp.async ring.
// ---------------------------------------------------------------------------
#define HT_BYTES (128*128)
#define HNS 3
#define HSM_TOTAL (2*HNS*HT_BYTES)   // 98304

template<bool HOUT>
__global__ __launch_bounds__(256) void h_gemm_kernel(
    const __half* __restrict__ A, const __half* __restrict__ Bt,
    void* __restrict__ Cv, int M, int N, int K)
{
    extern __shared__ char smem[];
    char* AsBase = smem;
    char* BsBase = smem + HNS * HT_BYTES;
    const unsigned smem32 = (unsigned)__cvta_generic_to_shared(smem);

    const int tid  = threadIdx.x;
    const int lane = tid & 31;
    const int warp = tid >> 5;
    const int wm   = warp >> 2;
    const int wn   = warp & 3;
    const int bm   = blockIdx.y * 128;
    const int bn   = blockIdx.x * 128;
    const int lq = lane >> 2;
    const int lr = lane & 3;

    const int a_rl = (lane & 7) + ((lane & 8) ? 8 : 0);
    const int a_ch = lane >> 4;
    const int b_rl = (lane & 7) + ((lane & 16) ? 8 : 0);
    const int b_ch = (lane >> 3) & 1;

    float acc[4][4][4];
    #pragma unroll
    for (int mt = 0; mt < 4; mt++)
        #pragma unroll
        for (int nt = 0; nt < 4; nt++)
            #pragma unroll
            for (int i = 0; i < 4; i++) acc[mt][nt][i] = 0.f;

    const int NK = K >> 6;

    auto fill = [&](int j, int s) {
        char* As = AsBase + s * HT_BYTES;
        char* Bs = BsBase + s * HT_BYTES;
        const __half* Ag = A  + (long)bm * K + j * 64;
        const __half* Bg = Bt + (long)bn * K + j * 64;
        #pragma unroll
        for (int l = 0; l < 4; l++) {
            int idx = tid + l * 256;
            int r = idx >> 3, c8 = idx & 7;
            int dst = r * 128 + ((c8 ^ (r & 7)) << 4);
            cp16(As + dst, Ag + (long)r * K + c8 * 8);
            cp16(Bs + dst, Bg + (long)r * K + c8 * 8);
        }
        CP_COMMIT();
    };

    fill(0, 0);
    if (NK > 1) fill(1, 1);

    int arow[4], brow[2];
    #pragma unroll
    for (int mt = 0; mt < 4; mt++) arow[mt] = wm * 64 + mt * 16 + a_rl;
    #pragma unroll
    for (int p = 0; p < 2; p++) brow[p] = wn * 32 + p * 16 + b_rl;

    for (int it = 0; it < NK; it++) {
        if (it + 1 < NK) { CP_WAIT(1); } else { CP_WAIT(0); }
        __syncthreads();
        if (it + 2 < NK) fill(it + 2, (it + 2) % 3);

        const unsigned Ab = smem32 + (it % 3) * HT_BYTES;
        const unsigned Bb = smem32 + (HNS + it % 3) * HT_BYTES;

        #pragma unroll
        for (int ks = 0; ks < 4; ks++) {
            unsigned a[4][4], b[4][2];
            #pragma unroll
            for (int mt = 0; mt < 4; mt++) {
                int ch = 2 * ks + a_ch;
                unsigned addr = Ab + arow[mt] * 128 + ((ch ^ (arow[mt] & 7)) << 4);
                ldmx4(a[mt][0], a[mt][1], a[mt][2], a[mt][3], addr);
            }
            #pragma unroll
            for (int p = 0; p < 2; p++) {
                int ch = 2 * ks + b_ch;
                unsigned addr = Bb + brow[p] * 128 + ((ch ^ (brow[p] & 7)) << 4);
                ldmx4(b[2*p][0], b[2*p][1], b[2*p+1][0], b[2*p+1][1], addr);
            }
            #pragma unroll
            for (int mt = 0; mt < 4; mt++)
                #pragma unroll
                for (int nt = 0; nt < 4; nt++)
                    mma_f16(acc[mt][nt], a[mt], b[nt]);
        }
        __syncthreads();
    }

    #pragma unroll
    for (int mt = 0; mt < 4; mt++) {
        long row0 = bm + wm * 64 + mt * 16 + lq;
        long row1 = row0 + 8;
        #pragma unroll
        for (int nt = 0; nt < 4; nt++) {
            int col = bn + wn * 32 + nt * 8 + 2 * lr;
            if (HOUT) {
                __half* C = (__half*)Cv;
                *reinterpret_cast<unsigned*>(&C[row0 * N + col]) =
                    pack_h2(acc[mt][nt][0], acc[mt][nt][1]);
                *reinterpret_cast<unsigned*>(&C[row1 * N + col]) =
                    pack_h2(acc[mt][nt][2], acc[mt][nt][3]);
            } else {
                float* C = (float*)Cv;
                *reinterpret_cast<float2*>(&C[row0 * N + col]) =
                    make_float2(acc[mt][nt][0], acc[mt][nt][1]);
                *reinterpret_cast<float2*>(&C[row1 * N + col]) =
                    make_float2(acc[mt][nt][2], acc[mt][nt][3]);
            }
        }
    }
}

// ---------------------------------------------------------------------------
// FP16 flash attention, K+V double-buffered single-group pipeline, causal.
// Grid (S/128, H, B), 256 threads (8 warps), warp = 16 q rows.
// Smem: Q 32K | K 2x16K | V 2x16K | P 16K = 112KB (2 CTAs/SM).
// ---------------------------------------------------------------------------
#define AQ_OFF 0
#define AK_OFF 32768
#define AV_OFF 65536
#define AP_OFF 98304
#define ATTN_SMEM_BYTES 114688

__device__ __forceinline__ float red_max4(float v) {
    v = fmaxf(v, __shfl_xor_sync(0xffffffffu, v, 1));
    v = fmaxf(v, __shfl_xor_sync(0xffffffffu, v, 2));
    return v;
}
__device__ __forceinline__ float red_sum4(float v) {
    v += __shfl_xor_sync(0xffffffffu, v, 1);
    v += __shfl_xor_sync(0xffffffffu, v, 2);
    return v;
}
__device__ __forceinline__ int sw256(int r, int c16) {
    return (c16 & 8) | ((c16 ^ r) & 7);
}

__global__ __launch_bounds__(256) void attn_h_kernel()
{
    extern __shared__ char smc[];
    char* Qs = smc + AQ_OFF;
    char* Ps = smc + AP_OFF;
    const unsigned smem32 = (unsigned)__cvta_generic_to_shared(smc);

    const int qt = (int)(gridDim.x - 1) - blockIdx.x;
    const int h  = blockIdx.y;
    const int b  = blockIdx.z;
    const int kvh = h / REP_;

    const int tid  = threadIdx.x;
    const int lane = tid & 31;
    const int w    = tid >> 5;
    const int lq   = lane >> 2;
    const int lr   = lane & 3;

    const int a_rl = (lane & 7) + ((lane & 8) ? 8 : 0);
    const int a_ch = lane >> 4;
    const int b_rl = (lane & 7) + ((lane & 16) ? 8 : 0);
    const int b_ch = (lane >> 3) & 1;

    const float SCL = 0.08838834764831845f * 1.4426950408889634f;
    const int nkt = 2 * qt + 2;

    const long rowbase = (long)(b * S_);
    const int qcol = h * 128;
    const int kcol = 2048 + kvh * 128;
    const int vcol = 2560 + kvh * 128;

    // KV tile loader (slot = t & 1), K and V in ONE group with caller's commit
    auto load_kv = [&](int t) {
        char* Kd = smc + AK_OFF + (t & 1) * 16384;
        char* Vd = smc + AV_OFF + (t & 1) * 16384;
        #pragma unroll
        for (int l = 0; l < 4; l++) {
            int i = tid + l * 256;
            int r = i >> 4, c16 = i & 15;
            int dst = r * 256 + (sw256(r & 7, c16) << 4);
            cp16(Kd + dst, &g_qkv[(rowbase + t * 64 + r) * QKV_N + kcol + c16 * 8]);
            cp16(Vd + dst, &g_qkv[(rowbase + t * 64 + r) * QKV_N + vcol + c16 * 8]);
        }
        CP_COMMIT();
    };

    // prologue: Q + K0 + V0 as one group
    #pragma unroll
    for (int l = 0; l < 8; l++) {
        int i = tid + l * 256;
        int r = i >> 4, c16 = i & 15;
        cp16(Qs + r * 256 + (sw256(r & 7, c16) << 4),
             &g_qkv[(rowbase + qt * 128 + r) * QKV_N + qcol + c16 * 8]);
    }
    load_kv(0);

    float o[16][4];
    #pragma unroll
    for (int nt = 0; nt < 16; nt++)
        #pragma unroll
        for (int j = 0; j < 4; j++) o[nt][j] = 0.f;
    float m0 = -1e30f, m1 = -1e30f, l0 = 0.f, l1 = 0.f;

    const int qrow = w * 16 + lq;
    const int aqrow = w * 16 + a_rl;
    const int vt = lane >> 3;
    const int vl = lane & 7;

    for (int kt = 0; kt < nkt; kt++) {
        __syncthreads();   // all warps done with iter kt-1 (slots (kt+1)&1 free)
        if (kt + 1 < nkt) { load_kv(kt + 1); CP_WAIT(1); }
        else              { CP_WAIT(0); }
        __syncthreads();   // group kt visible to all threads

        const unsigned Kb = smem32 + AK_OFF + (kt & 1) * 16384;
        const unsigned Vb = smem32 + AV_OFF + (kt & 1) * 16384;
        const unsigned Qb = smem32 + AQ_OFF;

        // ---- scores: S = Q K^T ----
        float sacc[8][4];
        #pragma unroll
        for (int nt = 0; nt < 8; nt++)
            #pragma unroll
            for (int j = 0; j < 4; j++) sacc[nt][j] = 0.f;

        #pragma unroll
        for (int ks = 0; ks < 8; ks++) {
            unsigned a[4];
            {
                int ch = 2 * ks + a_ch;
                unsigned addr = Qb + aqrow * 256 + (sw256(aqrow & 7, ch) << 4);
                ldmx4(a[0], a[1], a[2], a[3], addr);
            }
            #pragma unroll
            for (int p = 0; p < 4; p++) {
                int row = p * 16 + b_rl;
                int ch = 2 * ks + b_ch;
                unsigned addr = Kb + row * 256 + (sw256(row & 7, ch) << 4);
                unsigned b0[2], b1[2];
                ldmx4(b0[0], b0[1], b1[0], b1[1], addr);
                mma_f16(sacc[2*p],     a, b0);
                mma_f16(sacc[2*p + 1], a, b1);
            }
        }

        #pragma unroll
        for (int nt = 0; nt < 8; nt++)
            #pragma unroll
            for (int j = 0; j < 4; j++) sacc[nt][j] *= SCL;

        if (kt >= 2 * qt) {
            int r0 = qt * 128 + qrow;
            int r1 = r0 + 8;
            #pragma unroll
            for (int nt = 0; nt < 8; nt++) {
                int c = kt * 64 + nt * 8 + 2 * lr;
                if (c     > r0) sacc[nt][0] = -1e30f;
                if (c + 1 > r0) sacc[nt][1] = -1e30f;
                if (c     > r1) sacc[nt][2] = -1e30f;
                if (c + 1 > r1) sacc[nt][3] = -1e30f;
            }
        }

        // ---- online softmax (base-2) ----
        float mt0 = -1e30f, mt1 = -1e30f;
        #pragma unroll
        for (int nt = 0; nt < 8; nt++) {
            mt0 = fmaxf(mt0, fmaxf(sacc[nt][0], sacc[nt][1]));
            mt1 = fmaxf(mt1, fmaxf(sacc[nt][2], sacc[nt][3]));
        }
        mt0 = red_max4(mt0);
        mt1 = red_max4(mt1);
        float mn0 = fmaxf(m0, mt0), mn1 = fmaxf(m1, mt1);
        float alpha0 = ex2f(m0 - mn0), alpha1 = ex2f(m1 - mn1);

        float rs0 = 0.f, rs1 = 0.f;
        #pragma unroll
        for (int nt = 0; nt < 8; nt++) {
            sacc[nt][0] = ex2f(sacc[nt][0] - mn0);
            sacc[nt][1] = ex2f(sacc[nt][1] - mn0);
            sacc[nt][2] = ex2f(sacc[nt][2] - mn1);
            sacc[nt][3] = ex2f(sacc[nt][3] - mn1);
            rs0 += sacc[nt][0] + sacc[nt][1];
            rs1 += sacc[nt][2] + sacc[nt][3];
        }
        rs0 = red_sum4(rs0);
        rs1 = red_sum4(rs1);
        l0 = l0 * alpha0 + rs0;
        l1 = l1 * alpha1 + rs1;
        m0 = mn0; m1 = mn1;

        #pragma unroll
        for (int nt = 0; nt < 16; nt++) {
            o[nt][0] *= alpha0; o[nt][1] *= alpha0;
            o[nt][2] *= alpha1; o[nt][3] *= alpha1;
        }

        // ---- store P (per-warp private rows) ----
        #pragma unroll
        for (int nt = 0; nt < 8; nt++) {
            int sw = ((nt ^ lq) & 7) << 4;
            *reinterpret_cast<unsigned*>(Ps + qrow * 128 + sw + 4 * lr) =
                pack_h2(sacc[nt][0], sacc[nt][1]);
            *reinterpret_cast<unsigned*>(Ps + (qrow + 8) * 128 + sw + 4 * lr) =
                pack_h2(sacc[nt][2], sacc[nt][3]);
        }
        __syncwarp();

        // ---- O += P V ----
        const unsigned Pb = smem32 + AP_OFF;
        #pragma unroll
        for (int ks = 0; ks < 4; ks++) {
            unsigned a[4];
            {
                int ch = 2 * ks + a_ch;
                unsigned addr = Pb + aqrow * 128 + (((ch ^ (aqrow & 7)) & 7) << 4);
                ldmx4(a[0], a[1], a[2], a[3], addr);
            }
            const int vrow = ks * 16 + ((vt & 1) << 3) + vl;
            #pragma unroll
            for (int ntt = 0; ntt < 8; ntt++) {
                int c16 = 2 * ntt + (vt >> 1);
                unsigned addr = Vb + vrow * 256 + (sw256(vl, c16) << 4);
                unsigned v0, v1, v2, v3;
                ldmx4_trans(v0, v1, v2, v3, addr);
                unsigned b0[2] = {v0, v1};
                unsigned b1[2] = {v2, v3};
                mma_f16(o[2 * ntt],     a, b0);
                mma_f16(o[2 * ntt + 1], a, b1);
            }
        }
    }

    // ---- epilogue ----
    float inv0 = 1.0f / l0;
    float inv1 = 1.0f / l1;
    long base0 = (rowbase + qt * 128 + qrow) * (H_ * HD_) + h * HD_;
    long base1 = base0 + (long)8 * (H_ * HD_);
    #pragma unroll
    for (int nt = 0; nt < 16; nt++) {
        int c = nt * 8 + 2 * lr;
        *reinterpret_cast<unsigned*>(&g_attn[base0 + c]) =
            pack_h2(o[nt][0] * inv0, o[nt][1] * inv0);
        *reinterpret_cast<unsigned*>(&g_attn[base1 + c]) =
            pack_h2(o[nt][2] * inv1, o[nt][3] * inv1);
    }
}

// ---------------------------------------------------------------------------
extern "C" void kernel_launch(void* const* d_in, const int* in_sizes, int n_in,
                              void* d_out, int out_size)
{
    const float* x  = (const float*)d_in[0];
    const float* Wq = (const float*)d_in[1];
    const float* Wk = (const float*)d_in[2];
    const float* Wv = (const float*)d_in[3];
    const float* Wo = (const float*)d_in[4];
    float* out = (float*)d_out;

    __half *xh, *wqkv, *woh, *qkv, *attn;
    cudaGetSymbolAddress((void**)&xh,   g_xh);
    cudaGetSymbolAddress((void**)&wqkv, g_wqkv);
    cudaGetSymbolAddress((void**)&woh,  g_woh);
    cudaGetSymbolAddress((void**)&qkv,  g_qkv);
    cudaGetSymbolAddress((void**)&attn, g_attn);

    const int M = B_ * S_;   // 4096

    // prep: x convert + rope table (1 launch), all weight transposes (1 launch)
    prep_x_kernel<<<XCONV_BLOCKS + (S_*64)/256, 256>>>(x);
    prep_w_kernel<<<dim3(D_/32, 160), dim3(32, 8)>>>(Wq, Wk, Wv, Wo);

    cudaFuncSetAttribute(h_gemm_kernel<true>,
                         cudaFuncAttributeMaxDynamicSharedMemorySize, HSM_TOTAL);
    cudaFuncSetAttribute(h_gemm_kernel<false>,
                         cudaFuncAttributeMaxDynamicSharedMemorySize, HSM_TOTAL);

    // fused QKV projection
    h_gemm_kernel<true><<<dim3(QKV_N/128, M/128), 256, HSM_TOTAL>>>(
        xh, wqkv, qkv, M, QKV_N, D_);

    // RoPE (q + k heads) via table
    rope_qkv_kernel<<<(M * 20 * 64)/256, 256>>>();

    // Flash attention
    cudaFuncSetAttribute(attn_h_kernel,
                         cudaFuncAttributeMaxDynamicSharedMemorySize, ATTN_SMEM_BYTES);
    attn_h_kernel<<<dim3(S_/128, H_, B_), 256, ATTN_SMEM_BYTES>>>();

    // Output projection (fp32 out)
    h_gemm_kernel<false><<<dim3(D_/128, M/128), 256, HSM_TOTAL>>>(
        attn, woh, out, M, D_, D_);
}

// round 14
// speedup vs baseline: 8.8022x; 1.0448x over previous
#include <cuda_runtime.h>
#include <cuda_fp16.h>
#include <math.h>
#include <stdint.h>

#define B_ 2
#define S_ 2048
#define D_ 2048
#define H_ 16
#define KVH_ 4
#define HD_ 128
#define REP_ (H_/KVH_)
#define QKV_N 3072          // 2048 Q | 512 K | 512 V
#define SCLF 0.12752934082f  // log2e / sqrt(128)

// Scratch (device globals: allocation-free)
__device__ __half g_xh   [B_*S_*D_];
__device__ __half g_wqkv [QKV_N*D_];       // [N,K] fused Q|K|V weights
__device__ __half g_woh  [D_*H_*HD_];      // [N,K]
__device__ __half g_qkv  [B_*S_*QKV_N];    // fused projections
__device__ __half g_attn [B_*S_*H_*HD_];
__device__ float2 g_ropetab[S_*64];

// ---------------------------------------------------------------------------
// helpers
// ---------------------------------------------------------------------------
__device__ __forceinline__ float ex2f(float x) {
    float r;
    asm("ex2.approx.ftz.f32 %0, %1;" : "=f"(r) : "f"(x));
    return r;
}
__device__ __forceinline__ void mma_f16(
    float* c, const unsigned* a, const unsigned* b)
{
    asm volatile(
        "mma.sync.aligned.m16n8k16.row.col.f32.f16.f16.f32 "
        "{%0,%1,%2,%3}, {%4,%5,%6,%7}, {%8,%9}, {%0,%1,%2,%3};"
        : "+f"(c[0]), "+f"(c[1]), "+f"(c[2]), "+f"(c[3])
        : "r"(a[0]), "r"(a[1]), "r"(a[2]), "r"(a[3]),
          "r"(b[0]), "r"(b[1]));
}
__device__ __forceinline__ void cp16(void* s, const void* g) {
    unsigned sa = (unsigned)__cvta_generic_to_shared(s);
    asm volatile("cp.async.cg.shared.global [%0], [%1], 16;" :: "r"(sa), "l"(g));
}
#define CP_COMMIT()  asm volatile("cp.async.commit_group;")
#define CP_WAIT(n)   asm volatile("cp.async.wait_group %0;" :: "n"(n))

__device__ __forceinline__ void ldmx4(
    unsigned& r0, unsigned& r1, unsigned& r2, unsigned& r3, unsigned addr)
{
    asm volatile(
        "ldmatrix.sync.aligned.m8n8.x4.shared.b16 {%0,%1,%2,%3}, [%4];"
        : "=r"(r0), "=r"(r1), "=r"(r2), "=r"(r3) : "r"(addr));
}
__device__ __forceinline__ void ldmx4_trans(
    unsigned& r0, unsigned& r1, unsigned& r2, unsigned& r3, unsigned addr)
{
    asm volatile(
        "ldmatrix.sync.aligned.m8n8.x4.trans.shared.b16 {%0,%1,%2,%3}, [%4];"
        : "=r"(r0), "=r"(r1), "=r"(r2), "=r"(r3) : "r"(addr));
}
__device__ __forceinline__ unsigned pack_h2(float lo, float hi) {
    __half2 h = __floats2half2_rn(lo, hi);
    return *reinterpret_cast<unsigned*>(&h);
}

// ---------------------------------------------------------------------------
// prep (ONE launch, block 32x8):
//  y 0..159   : weight transposes (Wq/Wk/Wv/Wo -> [N,K] fp16)
//  y 160..295 : lin = (y-160)*64 + x : 0..8191 x-convert, 8192..8703 rope table
// ---------------------------------------------------------------------------
__global__ void prep_all_kernel(const float* __restrict__ x,
                                const float* __restrict__ Wq,
                                const float* __restrict__ Wk,
                                const float* __restrict__ Wv,
                                const float* __restrict__ Wo)
{
    const int yb = blockIdx.y;
    if (yb < 160) {
        __shared__ float t[32][33];
        const float* in; __half* out; int N; int n0;
        if (yb < 64)       { in = Wq; out = g_wqkv;             N = 2048; n0 = yb * 32; }
        else if (yb < 80)  { in = Wk; out = g_wqkv + 2048 * D_; N = 512;  n0 = (yb - 64) * 32; }
        else if (yb < 96)  { in = Wv; out = g_wqkv + 2560 * D_; N = 512;  n0 = (yb - 80) * 32; }
        else               { in = Wo; out = g_woh;              N = 2048; n0 = (yb - 96) * 32; }
        const int k0 = blockIdx.x * 32;
        const int tx = threadIdx.x, ty = threadIdx.y;
        #pragma unroll
        for (int i = 0; i < 32; i += 8)
            t[ty + i][tx] = in[(long)(k0 + ty + i) * N + n0 + tx];
        __syncthreads();
        #pragma unroll
        for (int i = 0; i < 32; i += 8)
            out[(long)(n0 + ty + i) * 2048 + k0 + tx] = __float2half_rn(t[tx][ty + i]);
    } else {
        const int lin = (yb - 160) * 64 + blockIdx.x;       // 0..8703
        const int tid = threadIdx.y * 32 + threadIdx.x;
        if (lin < 8192) {
            int i = lin * 256 + tid;                        // < B*S*D/4
            float4 v = reinterpret_cast<const float4*>(x)[i];
            uint2 u;
            u.x = pack_h2(v.x, v.y);
            u.y = pack_h2(v.z, v.w);
            reinterpret_cast<uint2*>(g_xh)[i] = u;
        } else {
            int id = (lin - 8192) * 256 + tid;              // < S*64
            int s = id >> 6, i = id & 63;
            float inv = exp2f(-(float)i * (13.287712379549449f / 64.0f));
            float sn, cs;
            sincosf((float)s * inv, &sn, &cs);
            g_ropetab[id] = make_float2(cs, sn);
        }
    }
}

// ---------------------------------------------------------------------------
// RoPE over fused qkv: 20 rotated heads (16 Q + 4 K); Q additionally scaled
// by log2e/sqrt(HD). Each thread: 4 consecutive rotation lanes (uint2 I/O).
// ---------------------------------------------------------------------------
__global__ void rope_qkv_kernel()
{
    long idx = (long)blockIdx.x * blockDim.x + threadIdx.x;  // M*20*16 threads
    int i4 = (int)(idx & 15) * 4;
    long t = idx >> 4;
    int h20 = (int)(t % 20);
    long row = t / 20;
    int s = (int)(row % S_);

    const float scl = (h20 < 16) ? SCLF : 1.0f;
    const int col = (h20 < 16) ? h20 * 128 : 2048 + (h20 - 16) * 128;
    __half* p = g_qkv + row * QKV_N + col;

    uint2 lo = *reinterpret_cast<uint2*>(p + i4);
    uint2 hi = *reinterpret_cast<uint2*>(p + i4 + 64);
    const __half2* lo2 = reinterpret_cast<const __half2*>(&lo);
    const __half2* hi2 = reinterpret_cast<const __half2*>(&hi);

    uint2 olo, ohi;
    unsigned* polo = reinterpret_cast<unsigned*>(&olo);
    unsigned* pohi = reinterpret_cast<unsigned*>(&ohi);
    #pragma unroll
    for (int j = 0; j < 2; j++) {
        float2 ta = g_ropetab[s * 64 + i4 + 2*j];
        float2 tb = g_ropetab[s * 64 + i4 + 2*j + 1];
        float x1a = __low2float(lo2[j]),  x1b = __high2float(lo2[j]);
        float x2a = __low2float(hi2[j]),  x2b = __high2float(hi2[j]);
        polo[j] = pack_h2((x1a * ta.x - x2a * ta.y) * scl,
                          (x1b * tb.x - x2b * tb.y) * scl);
        pohi[j] = pack_h2((x2a * ta.x + x1a * ta.y) * scl,
                          (x2b * tb.x + x1b * tb.y) * scl);
    }
    *reinterpret_cast<uint2*>(p + i4)      = olo;
    *reinterpret_cast<uint2*>(p + i4 + 64) = ohi;
}

// ---------------------------------------------------------------------------
// FP16 GEMM: C[M,N] = A[M,K] @ Bt[N,K]^T, fp32 accum, ldmatrix fragments.
// 256 threads (8 warps 2x4), CTA tile 128x128, BK=64, 3-stage cp.async ring.
// ONE __syncthreads per k-tile (post-compute barrier is redundant).
// ---------------------------------------------------------------------------
#define HT_BYTES (128*128)
#define HNS 3
#define HSM_TOTAL (2*HNS*HT_BYTES)   // 98304

template<bool HOUT>
__global__ __launch_bounds__(256) void h_gemm_kernel(
    const __half* __restrict__ A, const __half* __restrict__ Bt,
    void* __restrict__ Cv, int M, int N, int K)
{
    extern __shared__ char smem[];
    char* AsBase = smem;
    char* BsBase = smem + HNS * HT_BYTES;
    const unsigned smem32 = (unsigned)__cvta_generic_to_shared(smem);

    const int tid  = threadIdx.x;
    const int lane = tid & 31;
    const int warp = tid >> 5;
    const int wm   = warp >> 2;
    const int wn   = warp & 3;
    const int bm   = blockIdx.y * 128;
    const int bn   = blockIdx.x * 128;
    const int lq = lane >> 2;
    const int lr = lane & 3;

    const int a_rl = (lane & 7) + ((lane & 8) ? 8 : 0);
    const int a_ch = lane >> 4;
    const int b_rl = (lane & 7) + ((lane & 16) ? 8 : 0);
    const int b_ch = (lane >> 3) & 1;

    float acc[4][4][4];
    #pragma unroll
    for (int mt = 0; mt < 4; mt++)
        #pragma unroll
        for (int nt = 0; nt < 4; nt++)
            #pragma unroll
            for (int i = 0; i < 4; i++) acc[mt][nt][i] = 0.f;

    const int NK = K >> 6;

    auto fill = [&](int j, int s) {
        char* As = AsBase + s * HT_BYTES;
        char* Bs = BsBase + s * HT_BYTES;
        const __half* Ag = A  + (long)bm * K + j * 64;
        const __half* Bg = Bt + (long)bn * K + j * 64;
        #pragma unroll
        for (int l = 0; l < 4; l++) {
            int idx = tid + l * 256;
            int r = idx >> 3, c8 = idx & 7;
            int dst = r * 128 + ((c8 ^ (r & 7)) << 4);
            cp16(As + dst, Ag + (long)r * K + c8 * 8);
            cp16(Bs + dst, Bg + (long)r * K + c8 * 8);
        }
        CP_COMMIT();
    };

    fill(0, 0);
    if (NK > 1) fill(1, 1);

    int arow[4], brow[2];
    #pragma unroll
    for (int mt = 0; mt < 4; mt++) arow[mt] = wm * 64 + mt * 16 + a_rl;
    #pragma unroll
    for (int p = 0; p < 2; p++) brow[p] = wn * 32 + p * 16 + b_rl;

    for (int it = 0; it < NK; it++) {
        if (it + 1 < NK) { CP_WAIT(1); } else { CP_WAIT(0); }
        __syncthreads();     // group(it) visible + all warps done reading slot (it+2)%3
        if (it + 2 < NK) fill(it + 2, (it + 2) % 3);

        const unsigned Ab = smem32 + (it % 3) * HT_BYTES;
        const unsigned Bb = smem32 + (HNS + it % 3) * HT_BYTES;

        #pragma unroll
        for (int ks = 0; ks < 4; ks++) {
            unsigned a[4][4], b[4][2];
            #pragma unroll
            for (int mt = 0; mt < 4; mt++) {
                int ch = 2 * ks + a_ch;
                unsigned addr = Ab + arow[mt] * 128 + ((ch ^ (arow[mt] & 7)) << 4);
                ldmx4(a[mt][0], a[mt][1], a[mt][2], a[mt][3], addr);
            }
            #pragma unroll
            for (int p = 0; p < 2; p++) {
                int ch = 2 * ks + b_ch;
                unsigned addr = Bb + brow[p] * 128 + ((ch ^ (brow[p] & 7)) << 4);
                ldmx4(b[2*p][0], b[2*p][1], b[2*p+1][0], b[2*p+1][1], addr);
            }
            #pragma unroll
            for (int mt = 0; mt < 4; mt++)
                #pragma unroll
                for (int nt = 0; nt < 4; nt++)
                    mma_f16(acc[mt][nt], a[mt], b[nt]);
        }
        // no trailing barrier: next iteration's post-wait sync covers the hazard
    }

    #pragma unroll
    for (int mt = 0; mt < 4; mt++) {
        long row0 = bm + wm * 64 + mt * 16 + lq;
        long row1 = row0 + 8;
        #pragma unroll
        for (int nt = 0; nt < 4; nt++) {
            int col = bn + wn * 32 + nt * 8 + 2 * lr;
            if (HOUT) {
                __half* C = (__half*)Cv;
                *reinterpret_cast<unsigned*>(&C[row0 * N + col]) =
                    pack_h2(acc[mt][nt][0], acc[mt][nt][1]);
                *reinterpret_cast<unsigned*>(&C[row1 * N + col]) =
                    pack_h2(acc[mt][nt][2], acc[mt][nt][3]);
            } else {
                float* C = (float*)Cv;
                *reinterpret_cast<float2*>(&C[row0 * N + col]) =
                    make_float2(acc[mt][nt][0], acc[mt][nt][1]);
                *reinterpret_cast<float2*>(&C[row1 * N + col]) =
                    make_float2(acc[mt][nt][2], acc[mt][nt][3]);
            }
        }
    }
}

// ---------------------------------------------------------------------------
// FP16 flash attention, K+V double-buffered, causal. Q pre-scaled by
// log2e/sqrt(HD) at rope time (no per-tile score scaling).
// Grid (S/128, H, B), 256 threads (8 warps), warp = 16 q rows.
// ---------------------------------------------------------------------------
#define AQ_OFF 0
#define AK_OFF 32768
#define AV_OFF 65536
#define AP_OFF 98304
#define ATTN_SMEM_BYTES 114688

__device__ __forceinline__ float red_max4(float v) {
    v = fmaxf(v, __shfl_xor_sync(0xffffffffu, v, 1));
    v = fmaxf(v, __shfl_xor_sync(0xffffffffu, v, 2));
    return v;
}
__device__ __forceinline__ float red_sum4(float v) {
    v += __shfl_xor_sync(0xffffffffu, v, 1);
    v += __shfl_xor_sync(0xffffffffu, v, 2);
    return v;
}
__device__ __forceinline__ int sw256(int r, int c16) {
    return (c16 & 8) | ((c16 ^ r) & 7);
}

__global__ __launch_bounds__(256) void attn_h_kernel()
{
    extern __shared__ char smc[];
    char* Qs = smc + AQ_OFF;
    char* Ps = smc + AP_OFF;
    const unsigned smem32 = (unsigned)__cvta_generic_to_shared(smc);

    const int qt = (int)(gridDim.x - 1) - blockIdx.x;
    const int h  = blockIdx.y;
    const int b  = blockIdx.z;
    const int kvh = h / REP_;

    const int tid  = threadIdx.x;
    const int lane = tid & 31;
    const int w    = tid >> 5;
    const int lq   = lane >> 2;
    const int lr   = lane & 3;

    const int a_rl = (lane & 7) + ((lane & 8) ? 8 : 0);
    const int a_ch = lane >> 4;
    const int b_rl = (lane & 7) + ((lane & 16) ? 8 : 0);
    const int b_ch = (lane >> 3) & 1;

    const int nkt = 2 * qt + 2;

    const long rowbase = (long)(b * S_);
    const int qcol = h * 128;
    const int kcol = 2048 + kvh * 128;
    const int vcol = 2560 + kvh * 128;

    auto load_kv = [&](int t) {
        char* Kd = smc + AK_OFF + (t & 1) * 16384;
        char* Vd = smc + AV_OFF + (t & 1) * 16384;
        #pragma unroll
        for (int l = 0; l < 4; l++) {
            int i = tid + l * 256;
            int r = i >> 4, c16 = i & 15;
            int dst = r * 256 + (sw256(r & 7, c16) << 4);
            cp16(Kd + dst, &g_qkv[(rowbase + t * 64 + r) * QKV_N + kcol + c16 * 8]);
            cp16(Vd + dst, &g_qkv[(rowbase + t * 64 + r) * QKV_N + vcol + c16 * 8]);
        }
        CP_COMMIT();
    };

    #pragma unroll
    for (int l = 0; l < 8; l++) {
        int i = tid + l * 256;
        int r = i >> 4, c16 = i & 15;
        cp16(Qs + r * 256 + (sw256(r & 7, c16) << 4),
             &g_qkv[(rowbase + qt * 128 + r) * QKV_N + qcol + c16 * 8]);
    }
    load_kv(0);

    float o[16][4];
    #pragma unroll
    for (int nt = 0; nt < 16; nt++)
        #pragma unroll
        for (int j = 0; j < 4; j++) o[nt][j] = 0.f;
    float m0 = -1e30f, m1 = -1e30f, l0 = 0.f, l1 = 0.f;

    const int qrow = w * 16 + lq;
    const int aqrow = w * 16 + a_rl;
    const int vt = lane >> 3;
    const int vl = lane & 7;

    for (int kt = 0; kt < nkt; kt++) {
        __syncthreads();
        if (kt + 1 < nkt) { load_kv(kt + 1); CP_WAIT(1); }
        else              { CP_WAIT(0); }
        __syncthreads();

        const unsigned Kb = smem32 + AK_OFF + (kt & 1) * 16384;
        const unsigned Vb = smem32 + AV_OFF + (kt & 1) * 16384;
        const unsigned Qb = smem32 + AQ_OFF;

        // ---- scores: S = Q K^T (already log2e-scaled via Q) ----
        float sacc[8][4];
        #pragma unroll
        for (int nt = 0; nt < 8; nt++)
            #pragma unroll
            for (int j = 0; j < 4; j++) sacc[nt][j] = 0.f;

        #pragma unroll
        for (int ks = 0; ks < 8; ks++) {
            unsigned a[4];
            {
                int ch = 2 * ks + a_ch;
                unsigned addr = Qb + aqrow * 256 + (sw256(aqrow & 7, ch) << 4);
                ldmx4(a[0], a[1], a[2], a[3], addr);
            }
            #pragma unroll
            for (int p = 0; p < 4; p++) {
                int row = p * 16 + b_rl;
                int ch = 2 * ks + b_ch;
                unsigned addr = Kb + row * 256 + (sw256(row & 7, ch) << 4);
                unsigned b0[2], b1[2];
                ldmx4(b0[0], b0[1], b1[0], b1[1], addr);
                mma_f16(sacc[2*p],     a, b0);
                mma_f16(sacc[2*p + 1], a, b1);
            }
        }

        if (kt >= 2 * qt) {
            int r0 = qt * 128 + qrow;
            int r1 = r0 + 8;
            #pragma unroll
            for (int nt = 0; nt < 8; nt++) {
                int c = kt * 64 + nt * 8 + 2 * lr;
                if (c     > r0) sacc[nt][0] = -1e30f;
                if (c + 1 > r0) sacc[nt][1] = -1e30f;
                if (c     > r1) sacc[nt][2] = -1e30f;
                if (c + 1 > r1) sacc[nt][3] = -1e30f;
            }
        }

        // ---- online softmax (base-2) ----
        float mt0 = -1e30f, mt1 = -1e30f;
        #pragma unroll
        for (int nt = 0; nt < 8; nt++) {
            mt0 = fmaxf(mt0, fmaxf(sacc[nt][0], sacc[nt][1]));
            mt1 = fmaxf(mt1, fmaxf(sacc[nt][2], sacc[nt][3]));
        }
        mt0 = red_max4(mt0);
        mt1 = red_max4(mt1);
        float mn0 = fmaxf(m0, mt0), mn1 = fmaxf(m1, mt1);
        float alpha0 = ex2f(m0 - mn0), alpha1 = ex2f(m1 - mn1);

        float rs0 = 0.f, rs1 = 0.f;
        #pragma unroll
        for (int nt = 0; nt < 8; nt++) {
            sacc[nt][0] = ex2f(sacc[nt][0] - mn0);
            sacc[nt][1] = ex2f(sacc[nt][1] - mn0);
            sacc[nt][2] = ex2f(sacc[nt][2] - mn1);
            sacc[nt][3] = ex2f(sacc[nt][3] - mn1);
            rs0 += sacc[nt][0] + sacc[nt][1];
            rs1 += sacc[nt][2] + sacc[nt][3];
        }
        rs0 = red_sum4(rs0);
        rs1 = red_sum4(rs1);
        l0 = l0 * alpha0 + rs0;
        l1 = l1 * alpha1 + rs1;
        m0 = mn0; m1 = mn1;

        #pragma unroll
        for (int nt = 0; nt < 16; nt++) {
            o[nt][0] *= alpha0; o[nt][1] *= alpha0;
            o[nt][2] *= alpha1; o[nt][3] *= alpha1;
        }

        // ---- store P (per-warp private rows) ----
        #pragma unroll
        for (int nt = 0; nt < 8; nt++) {
            int sw = ((nt ^ lq) & 7) << 4;
            *reinterpret_cast<unsigned*>(Ps + qrow * 128 + sw + 4 * lr) =
                pack_h2(sacc[nt][0], sacc[nt][1]);
            *reinterpret_cast<unsigned*>(Ps + (qrow + 8) * 128 + sw + 4 * lr) =
                pack_h2(sacc[nt][2], sacc[nt][3]);
        }
        __syncwarp();

        // ---- O += P V ----
        const unsigned Pb = smem32 + AP_OFF;
        #pragma unroll
        for (int ks = 0; ks < 4; ks++) {
            unsigned a[4];
            {
                int ch = 2 * ks + a_ch;
                unsigned addr = Pb + aqrow * 128 + (((ch ^ (aqrow & 7)) & 7) << 4);
                ldmx4(a[0], a[1], a[2], a[3], addr);
            }
            const int vrow = ks * 16 + ((vt & 1) << 3) + vl;
            #pragma unroll
            for (int ntt = 0; ntt < 8; ntt++) {
                int c16 = 2 * ntt + (vt >> 1);
                unsigned addr = Vb + vrow * 256 + (sw256(vl, c16) << 4);
                unsigned v0, v1, v2, v3;
                ldmx4_trans(v0, v1, v2, v3, addr);
                unsigned b0[2] = {v0, v1};
                unsigned b1[2] = {v2, v3};
                mma_f16(o[2 * ntt],     a, b0);
                mma_f16(o[2 * ntt + 1], a, b1);
            }
        }
    }

    // ---- epilogue ----
    float inv0 = 1.0f / l0;
    float inv1 = 1.0f / l1;
    long base0 = (rowbase + qt * 128 + qrow) * (H_ * HD_) + h * HD_;
    long base1 = base0 + (long)8 * (H_ * HD_);
    #pragma unroll
    for (int nt = 0; nt < 16; nt++) {
        int c = nt * 8 + 2 * lr;
        *reinterpret_cast<unsigned*>(&g_attn[base0 + c]) =
            pack_h2(o[nt][0] * inv0, o[nt][1] * inv0);
        *reinterpret_cast<unsigned*>(&g_attn[base1 + c]) =
            pack_h2(o[nt][2] * inv1, o[nt][3] * inv1);
    }
}

// ---------------------------------------------------------------------------
extern "C" void kernel_launch(void* const* d_in, const int* in_sizes, int n_in,
                              void* d_out, int out_size)
{
    const float* x  = (const float*)d_in[0];
    const float* Wq = (const float*)d_in[1];
    const float* Wk = (const float*)d_in[2];
    const float* Wv = (const float*)d_in[3];
    const float* Wo = (const float*)d_in[4];
    float* out = (float*)d_out;

    __half *xh, *wqkv, *woh, *qkv, *attn;
    cudaGetSymbolAddress((void**)&xh,   g_xh);
    cudaGetSymbolAddress((void**)&wqkv, g_wqkv);
    cudaGetSymbolAddress((void**)&woh,  g_woh);
    cudaGetSymbolAddress((void**)&qkv,  g_qkv);
    cudaGetSymbolAddress((void**)&attn, g_attn);

    const int M = B_ * S_;   // 4096

    // all prep in ONE launch
    prep_all_kernel<<<dim3(64, 296), dim3(32, 8)>>>(x, Wq, Wk, Wv, Wo);

    cudaFuncSetAttribute(h_gemm_kernel<true>,
                         cudaFuncAttributeMaxDynamicSharedMemorySize, HSM_TOTAL);
    cudaFuncSetAttribute(h_gemm_kernel<false>,
                         cudaFuncAttributeMaxDynamicSharedMemorySize, HSM_TOTAL);

    // fused QKV projection
    h_gemm_kernel<true><<<dim3(QKV_N/128, M/128), 256, HSM_TOTAL>>>(
        xh, wqkv, qkv, M, QKV_N, D_);

    // RoPE (q + k heads), vectorized, Q pre-scaled
    rope_qkv_kernel<<<(M * 20 * 16)/256, 256>>>();

    // Flash attention
    cudaFuncSetAttribute(attn_h_kernel,
                         cudaFuncAttributeMaxDynamicSharedMemorySize, ATTN_SMEM_BYTES);
    attn_h_kernel<<<dim3(S_/128, H_, B_), 256, ATTN_SMEM_BYTES>>>();

    // Output projection (fp32 out)
    h_gemm_kernel<false><<<dim3(D_/128, M/128), 256, HSM_TOTAL>>>(
        attn, woh, out, M, D_, D_);
}